// round 1
// baseline (speedup 1.0000x reference)
#include <cuda_runtime.h>
#include <math.h>

#define SEQ   512
#define BATCH 64
#define INDIM 1024
#define HID   1024
#define NBLK  128   // persistent recurrence CTAs (single wave on 148 SMs)
#define JPB   8     // hidden rows per CTA (NBLK * JPB == HID)

// ---------------------------------------------------------------------------
// Grid barrier state (reset by init kernel at the start of every launch so the
// correctness call, capture call, and every replay behave identically).
// ---------------------------------------------------------------------------
__device__ unsigned g_count;
__device__ volatile unsigned g_phase;

__global__ void init_sync_kernel() {
    g_count = 0u;
    g_phase = 0u;
}

// ---------------------------------------------------------------------------
// Phase 1: C[m][n] = sum_k A[m][k]*B[n][k] + (b_ih[n]+b_hh[n])
// A = x  [M=SEQ*BATCH, K=INDIM] row-major
// B = W_ih [N=HID, K=INDIM] row-major
// C = d_out (xW staged in place; recurrence overwrites with h_t)
// 128x128 block tile, K-tile 8, 256 threads, 8x8 register tile per thread.
// ---------------------------------------------------------------------------
__global__ __launch_bounds__(256) void gemm_xw_kernel(
    const float* __restrict__ A,
    const float* __restrict__ B,
    const float* __restrict__ bih,
    const float* __restrict__ bhh,
    float* __restrict__ C)
{
    __shared__ float As[8][128];
    __shared__ float Bs[8][128];

    const int K  = INDIM;
    const int N  = HID;
    const int bm = blockIdx.y * 128;
    const int bn = blockIdx.x * 128;
    const int tid = threadIdx.x;

    const int lr = tid >> 1;          // 0..127 load row
    const int lc = (tid & 1) << 2;    // 0 or 4 (float4 within 8-wide k tile)
    const int tx = (tid & 15) << 3;   // output col offset 0..120
    const int ty = (tid >> 4) << 3;   // output row offset 0..120

    const float* Aptr = A + (size_t)(bm + lr) * K + lc;
    const float* Bptr = B + (size_t)(bn + lr) * K + lc;

    float acc[8][8];
#pragma unroll
    for (int i = 0; i < 8; i++)
#pragma unroll
        for (int j = 0; j < 8; j++) acc[i][j] = 0.0f;

    for (int k0 = 0; k0 < K; k0 += 8) {
        float4 av = *(const float4*)(Aptr + k0);
        float4 bv = *(const float4*)(Bptr + k0);
        As[lc + 0][lr] = av.x; As[lc + 1][lr] = av.y;
        As[lc + 2][lr] = av.z; As[lc + 3][lr] = av.w;
        Bs[lc + 0][lr] = bv.x; Bs[lc + 1][lr] = bv.y;
        Bs[lc + 2][lr] = bv.z; Bs[lc + 3][lr] = bv.w;
        __syncthreads();

#pragma unroll
        for (int kk = 0; kk < 8; kk++) {
            float a[8], b[8];
            *(float4*)(a)     = *(const float4*)&As[kk][ty];
            *(float4*)(a + 4) = *(const float4*)&As[kk][ty + 4];
            *(float4*)(b)     = *(const float4*)&Bs[kk][tx];
            *(float4*)(b + 4) = *(const float4*)&Bs[kk][tx + 4];
#pragma unroll
            for (int i = 0; i < 8; i++)
#pragma unroll
                for (int j = 0; j < 8; j++)
                    acc[i][j] = fmaf(a[i], b[j], acc[i][j]);
        }
        __syncthreads();
    }

    float bias[8];
#pragma unroll
    for (int j = 0; j < 8; j++) {
        int n = bn + tx + j;
        bias[j] = bih[n] + bhh[n];
    }

#pragma unroll
    for (int i = 0; i < 8; i++) {
        float* crow = C + (size_t)(bm + ty + i) * N + bn + tx;
        float4 v0, v1;
        v0.x = acc[i][0] + bias[0]; v0.y = acc[i][1] + bias[1];
        v0.z = acc[i][2] + bias[2]; v0.w = acc[i][3] + bias[3];
        v1.x = acc[i][4] + bias[4]; v1.y = acc[i][5] + bias[5];
        v1.z = acc[i][6] + bias[6]; v1.w = acc[i][7] + bias[7];
        *(float4*)(crow)     = v0;
        *(float4*)(crow + 4) = v1;
    }
}

// ---------------------------------------------------------------------------
// Phase 2: persistent recurrence.
//   out[t][b][j] = tanh( out[t][b][j](=xw) + sum_k out[t-1][b][k] * W_hh[j][k] )
// 128 CTAs x 256 threads. CTA owns JPB=8 rows of W_hh in SMEM (warp w -> row w,
// so the W read is a uniform broadcast, no padding needed). h_{t-1} staged in
// 64-wide k chunks. Grid barrier between steps.
// Dynamic SMEM: Ws[8*1024] + hs[64][65]  (49408 B > 48K static limit).
// ---------------------------------------------------------------------------
__global__ __launch_bounds__(256) void rnn_recurrence_kernel(
    const float* __restrict__ W,
    float* __restrict__ out)
{
    extern __shared__ float smem[];
    float* Ws = smem;                                  // [JPB][1024]
    float (*hs)[65] = (float(*)[65])(smem + JPB * HID); // [64][65] padded

    const int tid  = threadIdx.x;
    const int jj   = tid >> 5;        // warp id 0..7 -> local j row
    const int lane = tid & 31;
    const int j    = blockIdx.x * JPB + jj;
    const int b0   = lane;
    const int b1   = lane + 32;

    // Load this warp's W_hh row into SMEM.
    {
        const float* wrow = W + (size_t)j * HID;
        for (int c = lane * 4; c < HID; c += 128) {
            float4 v = *(const float4*)(wrow + c);
            *(float4*)&Ws[jj * HID + c] = v;
        }
    }
    __syncthreads();

    for (int t = 0; t < SEQ; t++) {
        float a0 = 0.f, a1 = 0.f, a2 = 0.f, a3 = 0.f;

        if (t > 0) {
            const float* hprev = out + (size_t)(t - 1) * BATCH * HID;
            for (int kc = 0; kc < HID; kc += 64) {
                __syncthreads();  // protect hs reuse
                // stage hs[64 b][64 k]
                {
                    int i = tid * 4;  // 0..1020
#pragma unroll
                    for (int r = 0; r < 4; r++, i += 1024) {
                        int b = i >> 6;
                        int k = i & 63;
                        float4 v = *(const float4*)(hprev + (size_t)b * HID + kc + k);
                        float* dst = &hs[b][k];
                        dst[0] = v.x; dst[1] = v.y; dst[2] = v.z; dst[3] = v.w;
                    }
                }
                __syncthreads();

                const float* wrow = &Ws[jj * HID + kc];
#pragma unroll
                for (int k = 0; k < 64; k += 2) {
                    float w0 = wrow[k];
                    float w1 = wrow[k + 1];
                    a0 = fmaf(hs[b0][k],     w0, a0);
                    a1 = fmaf(hs[b1][k],     w0, a1);
                    a2 = fmaf(hs[b0][k + 1], w1, a2);
                    a3 = fmaf(hs[b1][k + 1], w1, a3);
                }
            }
        }

        float* orow = out + (size_t)t * BATCH * HID;
        const size_t i0 = (size_t)b0 * HID + j;
        const size_t i1 = (size_t)b1 * HID + j;
        orow[i0] = tanhf(orow[i0] + (a0 + a2));
        orow[i1] = tanhf(orow[i1] + (a1 + a3));

        // grid barrier (skip after last step; next launch is stream-ordered)
        if (t < SEQ - 1) {
            __syncthreads();
            if (tid == 0) {
                __threadfence();
                if (atomicAdd(&g_count, 1u) == (unsigned)(gridDim.x - 1)) {
                    atomicExch(&g_count, 0u);
                    __threadfence();
                    g_phase = (unsigned)(t + 1);
                } else {
                    while (g_phase < (unsigned)(t + 1)) { }
                    __threadfence();
                }
            }
            __syncthreads();
        }
    }
}

// ---------------------------------------------------------------------------
// Phase 3: h_n = out[SEQ-1]  (64*1024 floats appended after out)
// ---------------------------------------------------------------------------
__global__ void copy_hn_kernel(const float* __restrict__ src,
                               float* __restrict__ dst)
{
    int i = blockIdx.x * blockDim.x + threadIdx.x;  // float4 index
    float4 v = ((const float4*)src)[i];
    ((float4*)dst)[i] = v;
}

// ---------------------------------------------------------------------------
extern "C" void kernel_launch(void* const* d_in, const int* in_sizes, int n_in,
                              void* d_out, int out_size)
{
    (void)in_sizes; (void)n_in; (void)out_size;
    const float* x    = (const float*)d_in[0];
    const float* W_ih = (const float*)d_in[1];
    const float* W_hh = (const float*)d_in[2];
    const float* b_ih = (const float*)d_in[3];
    const float* b_hh = (const float*)d_in[4];
    float* out = (float*)d_out;

    // Opt-in dynamic SMEM for the persistent kernel (49408 B). Idempotent,
    // not a stream op, graph-capture safe.
    const int shbytes = (JPB * HID + 64 * 65) * (int)sizeof(float);
    cudaFuncSetAttribute(rnn_recurrence_kernel,
                         cudaFuncAttributeMaxDynamicSharedMemorySize, shbytes);

    // Reset barrier state every call (deterministic across capture/replay).
    init_sync_kernel<<<1, 1>>>();

    // Phase 1: xW + bias -> out[t] for all t.
    dim3 g1(HID / 128, (SEQ * BATCH) / 128);
    gemm_xw_kernel<<<g1, 256>>>(x, W_ih, b_ih, b_hh, out);

    // Phase 2: persistent recurrence, in place on out.
    rnn_recurrence_kernel<<<NBLK, 256, shbytes>>>(W_hh, out);

    // Phase 3: append h_n = out[SEQ-1].
    copy_hn_kernel<<<(BATCH * HID / 4) / 256, 256>>>(
        out + (size_t)(SEQ - 1) * BATCH * HID,
        out + (size_t)SEQ * BATCH * HID);
}

// round 2
// speedup vs baseline: 1.6812x; 1.6812x over previous
#include <cuda_runtime.h>
#include <math.h>

#define SEQ   512
#define BATCH 64
#define INDIM 1024
#define HID   1024

// ---- recurrence config ----
#define RBLK     128   // persistent CTAs (single wave; 1 CTA/SM by SMEM)
#define RTHREADS 128   // 4 warps
#define JPB      8     // hidden rows per CTA (RBLK * JPB == HID)
#define CK       256   // k-chunk staged per buffer
#define HPITCH   260   // floats per hs row: 256 + 4 (16B aligned, conflict-free LDS.128)

// ---------------------------------------------------------------------------
// Grid barrier state (reset every launch -> deterministic under graph replay)
// ---------------------------------------------------------------------------
__device__ unsigned g_count;
__device__ volatile unsigned g_phase;

__global__ void init_sync_kernel() {
    g_count = 0u;
    g_phase = 0u;
}

// ---------------------------------------------------------------------------
// cp.async helpers
// ---------------------------------------------------------------------------
__device__ __forceinline__ void cp_async16(void* smem_dst, const void* gsrc) {
    unsigned d = (unsigned)__cvta_generic_to_shared(smem_dst);
    asm volatile("cp.async.cg.shared.global [%0], [%1], 16;\n" :: "r"(d), "l"(gsrc));
}
__device__ __forceinline__ void cp_commit() {
    asm volatile("cp.async.commit_group;\n");
}
__device__ __forceinline__ void cp_wait0() {
    asm volatile("cp.async.wait_group 0;\n");
}
__device__ __forceinline__ void cp_wait1() {
    asm volatile("cp.async.wait_group 1;\n");
}

// ---------------------------------------------------------------------------
// Phase 1: C = x @ W_ih^T + (b_ih+b_hh)   (unchanged from Round 1)
// ---------------------------------------------------------------------------
__global__ __launch_bounds__(256) void gemm_xw_kernel(
    const float* __restrict__ A,
    const float* __restrict__ B,
    const float* __restrict__ bih,
    const float* __restrict__ bhh,
    float* __restrict__ C)
{
    __shared__ float As[8][128];
    __shared__ float Bs[8][128];

    const int K  = INDIM;
    const int N  = HID;
    const int bm = blockIdx.y * 128;
    const int bn = blockIdx.x * 128;
    const int tid = threadIdx.x;

    const int lr = tid >> 1;
    const int lc = (tid & 1) << 2;
    const int tx = (tid & 15) << 3;
    const int ty = (tid >> 4) << 3;

    const float* Aptr = A + (size_t)(bm + lr) * K + lc;
    const float* Bptr = B + (size_t)(bn + lr) * K + lc;

    float acc[8][8];
#pragma unroll
    for (int i = 0; i < 8; i++)
#pragma unroll
        for (int j = 0; j < 8; j++) acc[i][j] = 0.0f;

    for (int k0 = 0; k0 < K; k0 += 8) {
        float4 av = *(const float4*)(Aptr + k0);
        float4 bv = *(const float4*)(Bptr + k0);
        As[lc + 0][lr] = av.x; As[lc + 1][lr] = av.y;
        As[lc + 2][lr] = av.z; As[lc + 3][lr] = av.w;
        Bs[lc + 0][lr] = bv.x; Bs[lc + 1][lr] = bv.y;
        Bs[lc + 2][lr] = bv.z; Bs[lc + 3][lr] = bv.w;
        __syncthreads();

#pragma unroll
        for (int kk = 0; kk < 8; kk++) {
            float a[8], b[8];
            *(float4*)(a)     = *(const float4*)&As[kk][ty];
            *(float4*)(a + 4) = *(const float4*)&As[kk][ty + 4];
            *(float4*)(b)     = *(const float4*)&Bs[kk][tx];
            *(float4*)(b + 4) = *(const float4*)&Bs[kk][tx + 4];
#pragma unroll
            for (int i = 0; i < 8; i++)
#pragma unroll
                for (int j = 0; j < 8; j++)
                    acc[i][j] = fmaf(a[i], b[j], acc[i][j]);
        }
        __syncthreads();
    }

    float bias[8];
#pragma unroll
    for (int j = 0; j < 8; j++) {
        int n = bn + tx + j;
        bias[j] = bih[n] + bhh[n];
    }

#pragma unroll
    for (int i = 0; i < 8; i++) {
        float* crow = C + (size_t)(bm + ty + i) * N + bn + tx;
        float4 v0, v1;
        v0.x = acc[i][0] + bias[0]; v0.y = acc[i][1] + bias[1];
        v0.z = acc[i][2] + bias[2]; v0.w = acc[i][3] + bias[3];
        v1.x = acc[i][4] + bias[4]; v1.y = acc[i][5] + bias[5];
        v1.z = acc[i][6] + bias[6]; v1.w = acc[i][7] + bias[7];
        *(float4*)(crow)     = v0;
        *(float4*)(crow + 4) = v1;
    }
}

// ---------------------------------------------------------------------------
// Phase 2: persistent recurrence, FFMA-issue-bound layout.
//   thread = (b = tid&63, jg = tid>>6); computes out[t][b][j0..j0+3]
//   W rows resident in SMEM (read as uniform-broadcast LDS.128)
//   h staged [64][HPITCH] per 256-k chunk, double buffered via cp.async
// ---------------------------------------------------------------------------
__global__ __launch_bounds__(RTHREADS) void rnn_recurrence_kernel(
    const float* __restrict__ W,
    float* __restrict__ out)
{
    extern __shared__ float smem[];
    float* Ws = smem;                       // [JPB][HID] = 32KB
    float* hs = smem + JPB * HID;           // [2][64][HPITCH]

    const int tid = threadIdx.x;
    const int b   = tid & 63;
    const int jg  = tid >> 6;               // 0 or 1 (uniform per warp)
    const int j0  = blockIdx.x * JPB + jg * 4;

    // Load this CTA's 8 W rows once (coalesced float4).
    {
        const float4* src = (const float4*)(W + (size_t)blockIdx.x * JPB * HID);
        float4* dst = (float4*)Ws;
#pragma unroll
        for (int u = 0; u < 16; u++)
            dst[tid + RTHREADS * u] = src[tid + RTHREADS * u];
    }
    __syncthreads();

    // staging mapping: thread copies col-block ic (fixed), rows r0, r0+2, ...
    const int ic = tid & 63;          // float4 column within chunk
    const int r0 = tid >> 6;          // starting row (0 or 1)

    for (int t = 0; t < SEQ; t++) {
        float acc0 = 0.f, acc1 = 0.f, acc2 = 0.f, acc3 = 0.f;

        if (t > 0) {
            const float* hprev = out + (size_t)(t - 1) * BATCH * HID;

            // stage chunk 0 -> buf 0
            {
                int r = r0;
#pragma unroll
                for (int u = 0; u < 32; u++, r += 2)
                    cp_async16(hs + r * HPITCH + ic * 4,
                               hprev + (size_t)r * HID + ic * 4);
                cp_commit();
            }

            for (int c = 0; c < 4; c++) {
                if (c < 3) {  // prefetch next chunk into other buffer
                    float* buf = hs + ((c + 1) & 1) * 64 * HPITCH;
                    const float* src = hprev + (c + 1) * CK;
                    int r = r0;
#pragma unroll
                    for (int u = 0; u < 32; u++, r += 2)
                        cp_async16(buf + r * HPITCH + ic * 4,
                                   src + (size_t)r * HID + ic * 4);
                    cp_commit();
                    cp_wait1();   // chunk c complete (<=1 group pending)
                } else {
                    cp_wait0();
                }
                __syncthreads();

                const float4* hv  = (const float4*)(hs + (c & 1) * 64 * HPITCH + b * HPITCH);
                const float4* wr0 = (const float4*)(Ws + (size_t)(j0 % JPB + 0) * HID + c * CK);
                const float4* wr1 = (const float4*)(Ws + (size_t)(j0 % JPB + 1) * HID + c * CK);
                const float4* wr2 = (const float4*)(Ws + (size_t)(j0 % JPB + 2) * HID + c * CK);
                const float4* wr3 = (const float4*)(Ws + (size_t)(j0 % JPB + 3) * HID + c * CK);

#pragma unroll 4
                for (int kk = 0; kk < CK / 4; kk++) {
                    float4 h  = hv[kk];
                    float4 w0 = wr0[kk];
                    float4 w1 = wr1[kk];
                    float4 w2 = wr2[kk];
                    float4 w3 = wr3[kk];
                    // interleave accumulator chains (each chain hit every 4 instrs)
                    acc0 = fmaf(h.x, w0.x, acc0);
                    acc1 = fmaf(h.x, w1.x, acc1);
                    acc2 = fmaf(h.x, w2.x, acc2);
                    acc3 = fmaf(h.x, w3.x, acc3);
                    acc0 = fmaf(h.y, w0.y, acc0);
                    acc1 = fmaf(h.y, w1.y, acc1);
                    acc2 = fmaf(h.y, w2.y, acc2);
                    acc3 = fmaf(h.y, w3.y, acc3);
                    acc0 = fmaf(h.z, w0.z, acc0);
                    acc1 = fmaf(h.z, w1.z, acc1);
                    acc2 = fmaf(h.z, w2.z, acc2);
                    acc3 = fmaf(h.z, w3.z, acc3);
                    acc0 = fmaf(h.w, w0.w, acc0);
                    acc1 = fmaf(h.w, w1.w, acc1);
                    acc2 = fmaf(h.w, w2.w, acc2);
                    acc3 = fmaf(h.w, w3.w, acc3);
                }
                __syncthreads();  // buffer reuse protection
            }
        }

        // epilogue: out[t][b][j0..j0+3] = tanh(xw + acc)
        {
            float* orow = out + ((size_t)t * BATCH + b) * HID + j0;
            float4 xw = *(const float4*)orow;
            float4 hn;
            hn.x = tanhf(xw.x + acc0);
            hn.y = tanhf(xw.y + acc1);
            hn.z = tanhf(xw.z + acc2);
            hn.w = tanhf(xw.w + acc3);
            *(float4*)orow = hn;
        }

        if (t < SEQ - 1) {
            __syncthreads();
            if (tid == 0) {
                __threadfence();
                if (atomicAdd(&g_count, 1u) == (unsigned)(gridDim.x - 1)) {
                    atomicExch(&g_count, 0u);
                    __threadfence();
                    g_phase = (unsigned)(t + 1);
                } else {
                    while (g_phase < (unsigned)(t + 1)) { }
                    __threadfence();
                }
            }
            __syncthreads();
        }
    }
}

// ---------------------------------------------------------------------------
// Phase 3: h_n = out[SEQ-1]
// ---------------------------------------------------------------------------
__global__ void copy_hn_kernel(const float* __restrict__ src,
                               float* __restrict__ dst)
{
    int i = blockIdx.x * blockDim.x + threadIdx.x;
    float4 v = ((const float4*)src)[i];
    ((float4*)dst)[i] = v;
}

// ---------------------------------------------------------------------------
extern "C" void kernel_launch(void* const* d_in, const int* in_sizes, int n_in,
                              void* d_out, int out_size)
{
    (void)in_sizes; (void)n_in; (void)out_size;
    const float* x    = (const float*)d_in[0];
    const float* W_ih = (const float*)d_in[1];
    const float* W_hh = (const float*)d_in[2];
    const float* b_ih = (const float*)d_in[3];
    const float* b_hh = (const float*)d_in[4];
    float* out = (float*)d_out;

    // dynamic SMEM: Ws (8*1024) + hs (2*64*HPITCH) floats = 165888 bytes
    const int shbytes = (JPB * HID + 2 * 64 * HPITCH) * (int)sizeof(float);
    cudaFuncSetAttribute(rnn_recurrence_kernel,
                         cudaFuncAttributeMaxDynamicSharedMemorySize, shbytes);

    init_sync_kernel<<<1, 1>>>();

    dim3 g1(HID / 128, (SEQ * BATCH) / 128);
    gemm_xw_kernel<<<g1, 256>>>(x, W_ih, b_ih, b_hh, out);

    rnn_recurrence_kernel<<<RBLK, RTHREADS, shbytes>>>(W_hh, out);

    copy_hn_kernel<<<(BATCH * HID / 4) / 256, 256>>>(
        out + (size_t)(SEQ - 1) * BATCH * HID,
        out + (size_t)SEQ * BATCH * HID);
}

// round 3
// speedup vs baseline: 2.1438x; 1.2751x over previous
#include <cuda_runtime.h>
#include <math.h>

#define SEQ   512
#define BATCH 64
#define INDIM 1024
#define HID   1024

// ---- recurrence config ----
#define RBLK     128   // persistent CTAs (single wave)
#define RTHREADS 128   // 4 warps: warp w -> (kh = w>>1, brow0 = (w&1)*32)
#define JPB      8     // hidden rows per CTA
#define CK       128   // k per staged chunk
#define CKP      132   // chunk row pitch (== 4 mod 32 -> conflict-free LDS.128)
#define NCHUNK   4     // chunks per k-half (4*128 = 512)

// ---------------------------------------------------------------------------
__device__ unsigned g_count;
__device__ volatile unsigned g_phase;

__global__ void init_sync_kernel() {
    g_count = 0u;
    g_phase = 0u;
}

// ---------------------------------------------------------------------------
__device__ __forceinline__ void cp_async16(void* smem_dst, const void* gsrc) {
    unsigned d = (unsigned)__cvta_generic_to_shared(smem_dst);
    asm volatile("cp.async.cg.shared.global [%0], [%1], 16;\n" :: "r"(d), "l"(gsrc));
}
__device__ __forceinline__ void cp_commit() {
    asm volatile("cp.async.commit_group;\n");
}
__device__ __forceinline__ void cp_wait0() {
    asm volatile("cp.async.wait_group 0;\n");
}
__device__ __forceinline__ void cp_wait1() {
    asm volatile("cp.async.wait_group 1;\n");
}

// ---------------------------------------------------------------------------
// Phase 1: C = x @ W_ih^T + (b_ih+b_hh)   (unchanged)
// ---------------------------------------------------------------------------
__global__ __launch_bounds__(256) void gemm_xw_kernel(
    const float* __restrict__ A,
    const float* __restrict__ B,
    const float* __restrict__ bih,
    const float* __restrict__ bhh,
    float* __restrict__ C)
{
    __shared__ float As[8][128];
    __shared__ float Bs[8][128];

    const int K  = INDIM;
    const int N  = HID;
    const int bm = blockIdx.y * 128;
    const int bn = blockIdx.x * 128;
    const int tid = threadIdx.x;

    const int lr = tid >> 1;
    const int lc = (tid & 1) << 2;
    const int tx = (tid & 15) << 3;
    const int ty = (tid >> 4) << 3;

    const float* Aptr = A + (size_t)(bm + lr) * K + lc;
    const float* Bptr = B + (size_t)(bn + lr) * K + lc;

    float acc[8][8];
#pragma unroll
    for (int i = 0; i < 8; i++)
#pragma unroll
        for (int j = 0; j < 8; j++) acc[i][j] = 0.0f;

    for (int k0 = 0; k0 < K; k0 += 8) {
        float4 av = *(const float4*)(Aptr + k0);
        float4 bv = *(const float4*)(Bptr + k0);
        As[lc + 0][lr] = av.x; As[lc + 1][lr] = av.y;
        As[lc + 2][lr] = av.z; As[lc + 3][lr] = av.w;
        Bs[lc + 0][lr] = bv.x; Bs[lc + 1][lr] = bv.y;
        Bs[lc + 2][lr] = bv.z; Bs[lc + 3][lr] = bv.w;
        __syncthreads();

#pragma unroll
        for (int kk = 0; kk < 8; kk++) {
            float a[8], b[8];
            *(float4*)(a)     = *(const float4*)&As[kk][ty];
            *(float4*)(a + 4) = *(const float4*)&As[kk][ty + 4];
            *(float4*)(b)     = *(const float4*)&Bs[kk][tx];
            *(float4*)(b + 4) = *(const float4*)&Bs[kk][tx + 4];
#pragma unroll
            for (int i = 0; i < 8; i++)
#pragma unroll
                for (int j = 0; j < 8; j++)
                    acc[i][j] = fmaf(a[i], b[j], acc[i][j]);
        }
        __syncthreads();
    }

    float bias[8];
#pragma unroll
    for (int j = 0; j < 8; j++) {
        int n = bn + tx + j;
        bias[j] = bih[n] + bhh[n];
    }

#pragma unroll
    for (int i = 0; i < 8; i++) {
        float* crow = C + (size_t)(bm + ty + i) * N + bn + tx;
        float4 v0, v1;
        v0.x = acc[i][0] + bias[0]; v0.y = acc[i][1] + bias[1];
        v0.z = acc[i][2] + bias[2]; v0.w = acc[i][3] + bias[3];
        v1.x = acc[i][4] + bias[4]; v1.y = acc[i][5] + bias[5];
        v1.z = acc[i][6] + bias[6]; v1.w = acc[i][7] + bias[7];
        *(float4*)(crow)     = v0;
        *(float4*)(crow + 4) = v1;
    }
}

// ---------------------------------------------------------------------------
// Phase 2: persistent recurrence, k-split layout.
//   thread = (b = tid&63, kh = tid>>6); 8 accumulators (all JPB j rows),
//   k range [kh*512, kh*512+512) in 4 chunks of 128, double-buffered cp.async,
//   per-warp private staging (warp stages the 32 h-rows it reads) -> no
//   __syncthreads inside the k loop.
// SMEM: Ws[8][1024] | hs[4 warps][2 bufs][32][CKP] | scratch[2][64][12]
// ---------------------------------------------------------------------------
__global__ __launch_bounds__(RTHREADS) void rnn_recurrence_kernel(
    const float* __restrict__ W,
    float* __restrict__ out)
{
    extern __shared__ float smem[];
    float* Ws      = smem;                          // 8192 floats
    float* hs      = smem + JPB * HID;              // 4*2*32*CKP floats
    float* scratch = hs + 4 * 2 * 32 * CKP;         // 2*64*12 floats

    const int tid  = threadIdx.x;
    const int lane = tid & 31;
    const int wid  = tid >> 5;
    const int b    = tid & 63;
    const int kh   = tid >> 6;          // 0 or 1 (uniform per warp)
    const int brow0 = (wid & 1) * 32;   // h rows this warp stages/reads
    const int jbase = blockIdx.x * JPB;

    float* hsw = hs + wid * (2 * 32 * CKP);   // this warp's staging area

    // Load this CTA's 8 W rows (coalesced).
    {
        const float4* src = (const float4*)(W + (size_t)blockIdx.x * JPB * HID);
        float4* dst = (float4*)Ws;
#pragma unroll
        for (int u = 0; u < 16; u++)
            dst[tid + RTHREADS * u] = src[tid + RTHREADS * u];
    }
    __syncthreads();

    for (int t = 0; t < SEQ; t++) {
        // prefetch xw for this thread's outputs (consumed ~8K cycles later)
        float* orow = out + ((size_t)t * BATCH + b) * HID + jbase + kh * 4;
        float4 xw = *(const float4*)orow;

        float a0 = 0.f, a1 = 0.f, a2 = 0.f, a3 = 0.f;
        float a4 = 0.f, a5 = 0.f, a6 = 0.f, a7 = 0.f;

        if (t > 0) {
            const float* hprev = out + (size_t)(t - 1) * BATCH * HID;
            const int kbase = kh * 512;

            // stage chunk c into buffer (c&1): rows brow0..brow0+31
            auto stage = [&](int c) {
                float* buf = hsw + (c & 1) * 32 * CKP;
                const float* src = hprev + (size_t)brow0 * HID + kbase + c * CK + lane * 4;
#pragma unroll
                for (int r = 0; r < 32; r++)
                    cp_async16(buf + r * CKP + lane * 4, src + (size_t)r * HID);
                cp_commit();
            };

            stage(0);
            stage(1);

#pragma unroll
            for (int c = 0; c < NCHUNK; c++) {
                if (c < NCHUNK - 1) cp_wait1(); else cp_wait0();

                const float4* hv = (const float4*)(hsw + (c & 1) * 32 * CKP + lane * CKP);
                const int k0 = kbase + c * CK;
                const float4* w0 = (const float4*)(Ws + 0 * HID + k0);
                const float4* w1 = (const float4*)(Ws + 1 * HID + k0);
                const float4* w2 = (const float4*)(Ws + 2 * HID + k0);
                const float4* w3 = (const float4*)(Ws + 3 * HID + k0);
                const float4* w4 = (const float4*)(Ws + 4 * HID + k0);
                const float4* w5 = (const float4*)(Ws + 5 * HID + k0);
                const float4* w6 = (const float4*)(Ws + 6 * HID + k0);
                const float4* w7 = (const float4*)(Ws + 7 * HID + k0);

#pragma unroll 4
                for (int kk = 0; kk < CK / 4; kk++) {
                    float4 h  = hv[kk];
                    float4 v0 = w0[kk], v1 = w1[kk], v2 = w2[kk], v3 = w3[kk];
                    float4 v4 = w4[kk], v5 = w5[kk], v6 = w6[kk], v7 = w7[kk];
                    a0 = fmaf(h.x, v0.x, a0); a1 = fmaf(h.x, v1.x, a1);
                    a2 = fmaf(h.x, v2.x, a2); a3 = fmaf(h.x, v3.x, a3);
                    a4 = fmaf(h.x, v4.x, a4); a5 = fmaf(h.x, v5.x, a5);
                    a6 = fmaf(h.x, v6.x, a6); a7 = fmaf(h.x, v7.x, a7);
                    a0 = fmaf(h.y, v0.y, a0); a1 = fmaf(h.y, v1.y, a1);
                    a2 = fmaf(h.y, v2.y, a2); a3 = fmaf(h.y, v3.y, a3);
                    a4 = fmaf(h.y, v4.y, a4); a5 = fmaf(h.y, v5.y, a5);
                    a6 = fmaf(h.y, v6.y, a6); a7 = fmaf(h.y, v7.y, a7);
                    a0 = fmaf(h.z, v0.z, a0); a1 = fmaf(h.z, v1.z, a1);
                    a2 = fmaf(h.z, v2.z, a2); a3 = fmaf(h.z, v3.z, a3);
                    a4 = fmaf(h.z, v4.z, a4); a5 = fmaf(h.z, v5.z, a5);
                    a6 = fmaf(h.z, v6.z, a6); a7 = fmaf(h.z, v7.z, a7);
                    a0 = fmaf(h.w, v0.w, a0); a1 = fmaf(h.w, v1.w, a1);
                    a2 = fmaf(h.w, v2.w, a2); a3 = fmaf(h.w, v3.w, a3);
                    a4 = fmaf(h.w, v4.w, a4); a5 = fmaf(h.w, v5.w, a5);
                    a6 = fmaf(h.w, v6.w, a6); a7 = fmaf(h.w, v7.w, a7);
                }

                if (c + 2 < NCHUNK) stage(c + 2);
            }
        }

        // ---- epilogue: combine kh halves, tanh, store ----
        __syncthreads();  // scratch reuse guard (prev step's reads done)
        {
            float* slot = scratch + (size_t)(kh * 64 + b) * 12;
            *(float4*)(slot + 0) = make_float4(a0, a1, a2, a3);
            *(float4*)(slot + 4) = make_float4(a4, a5, a6, a7);
        }
        __syncthreads();
        {
            // thread (b,kh) finalizes j = jbase + kh*4 .. +3
            const float* other = scratch + (size_t)((1 - kh) * 64 + b) * 12 + kh * 4;
            float4 p = *(const float4*)other;
            float4 own = (kh == 0) ? make_float4(a0, a1, a2, a3)
                                   : make_float4(a4, a5, a6, a7);
            float4 r;
            r.x = tanhf(xw.x + own.x + p.x);
            r.y = tanhf(xw.y + own.y + p.y);
            r.z = tanhf(xw.z + own.z + p.z);
            r.w = tanhf(xw.w + own.w + p.w);
            *(float4*)orow = r;
        }

        // ---- grid barrier ----
        if (t < SEQ - 1) {
            __syncthreads();
            if (tid == 0) {
                __threadfence();
                if (atomicAdd(&g_count, 1u) == (unsigned)(gridDim.x - 1)) {
                    atomicExch(&g_count, 0u);
                    __threadfence();
                    g_phase = (unsigned)(t + 1);
                } else {
                    while (g_phase < (unsigned)(t + 1)) { }
                    __threadfence();
                }
            }
            __syncthreads();
        }
    }
}

// ---------------------------------------------------------------------------
__global__ void copy_hn_kernel(const float* __restrict__ src,
                               float* __restrict__ dst)
{
    int i = blockIdx.x * blockDim.x + threadIdx.x;
    float4 v = ((const float4*)src)[i];
    ((float4*)dst)[i] = v;
}

// ---------------------------------------------------------------------------
extern "C" void kernel_launch(void* const* d_in, const int* in_sizes, int n_in,
                              void* d_out, int out_size)
{
    (void)in_sizes; (void)n_in; (void)out_size;
    const float* x    = (const float*)d_in[0];
    const float* W_ih = (const float*)d_in[1];
    const float* W_hh = (const float*)d_in[2];
    const float* b_ih = (const float*)d_in[3];
    const float* b_hh = (const float*)d_in[4];
    float* out = (float*)d_out;

    // dynamic SMEM: Ws 8192 + hs 4*2*32*CKP + scratch 1536 floats
    const int shfloats = JPB * HID + 4 * 2 * 32 * CKP + 2 * 64 * 12;
    const int shbytes  = shfloats * (int)sizeof(float);   // 174080 B
    cudaFuncSetAttribute(rnn_recurrence_kernel,
                         cudaFuncAttributeMaxDynamicSharedMemorySize, shbytes);

    init_sync_kernel<<<1, 1>>>();

    dim3 g1(HID / 128, (SEQ * BATCH) / 128);
    gemm_xw_kernel<<<g1, 256>>>(x, W_ih, b_ih, b_hh, out);

    rnn_recurrence_kernel<<<RBLK, RTHREADS, shbytes>>>(W_hh, out);

    copy_hn_kernel<<<(BATCH * HID / 4) / 256, 256>>>(
        out + (size_t)(SEQ - 1) * BATCH * HID,
        out + (size_t)SEQ * BATCH * HID);
}

// round 5
// speedup vs baseline: 2.3876x; 1.1137x over previous
#include <cuda_runtime.h>
#include <math.h>
#include <cstdint>

#define SEQ   512
#define BATCH 64
#define INDIM 1024
#define HID   1024

// ---- recurrence config (unchanged from R3) ----
#define RBLK     128
#define RTHREADS 128
#define JPB      8
#define CK       128
#define CKP      132
#define NCHUNK   4

// ---- phase1 mma.sync tf32 GEMM config ----
#define BM 128
#define BN 128
#define BK 32
#define PITCH 36                  // floats per SMEM row (conflict-free frags)
#define TBUF (128 * PITCH)        // floats per tile buffer
#define SM_GEMM (4 * TBUF * 4)    // A[2] + B[2] buffers, bytes = 73728

// ---------------------------------------------------------------------------
__device__ unsigned g_count;
__device__ volatile unsigned g_phase;

__global__ void init_sync_kernel() {
    g_count = 0u;
    g_phase = 0u;
}

// ---------------------------------------------------------------------------
__device__ __forceinline__ void cp_async16(void* smem_dst, const void* gsrc) {
    unsigned d = (unsigned)__cvta_generic_to_shared(smem_dst);
    asm volatile("cp.async.cg.shared.global [%0], [%1], 16;\n" :: "r"(d), "l"(gsrc));
}
__device__ __forceinline__ void cp_commit() { asm volatile("cp.async.commit_group;\n"); }
__device__ __forceinline__ void cp_wait0()  { asm volatile("cp.async.wait_group 0;\n"); }
__device__ __forceinline__ void cp_wait1()  { asm volatile("cp.async.wait_group 1;\n"); }

__device__ __forceinline__ uint32_t f32_hi_bits(float v) {
    return __float_as_uint(v) & 0xFFFFE000u;
}

// D += A(16x8) * B(8x8), tf32 operands as b32 regs
__device__ __forceinline__ void mma_tf32(float* d,
                                         uint32_t a0, uint32_t a1, uint32_t a2, uint32_t a3,
                                         uint32_t b0, uint32_t b1) {
    asm volatile(
        "mma.sync.aligned.m16n8k8.row.col.f32.tf32.tf32.f32 "
        "{%0,%1,%2,%3}, {%4,%5,%6,%7}, {%8,%9}, {%0,%1,%2,%3};"
        : "+f"(d[0]), "+f"(d[1]), "+f"(d[2]), "+f"(d[3])
        : "r"(a0), "r"(a1), "r"(a2), "r"(a3), "r"(b0), "r"(b1));
}

// ---------------------------------------------------------------------------
// Phase 1: C = x @ W_ih^T + (b_ih + b_hh)  via mma.sync tf32, 3-pass split.
//   grid (BN tiles = 8, BM tiles = 256), 256 threads (8 warps, 2x4).
// ---------------------------------------------------------------------------
__global__ __launch_bounds__(256) void gemm_xw_mma_kernel(
    const float* __restrict__ A,     // x [32768, 1024] row-major
    const float* __restrict__ B,     // W_ih [1024, 1024] row-major
    const float* __restrict__ bih,
    const float* __restrict__ bhh,
    float* __restrict__ C)
{
    extern __shared__ float sm[];
    float* As = sm;              // [2][128][PITCH]
    float* Bs = sm + 2 * TBUF;   // [2][128][PITCH]

    const int tid    = threadIdx.x;
    const int lane   = tid & 31;
    const int wid    = tid >> 5;
    const int g      = lane >> 2;   // group 0..7
    const int tig    = lane & 3;    // thread-in-group
    const int warp_m = wid & 1;     // 0..1  (x64 rows)
    const int warp_n = wid >> 1;    // 0..3  (x32 cols)
    const int bm     = blockIdx.y * BM;
    const int bn     = blockIdx.x * BN;

    float acc[4][4][4];
#pragma unroll
    for (int i = 0; i < 4; i++)
#pragma unroll
        for (int j = 0; j < 4; j++)
#pragma unroll
            for (int c = 0; c < 4; c++) acc[i][j][c] = 0.0f;

    // staging: 1024 float4 per tile, 256 threads -> 4 float4 each per tile
    const int srow = tid >> 3;        // base row step: i>>3 with i=tid+256u
    const int skq  = tid & 7;         // float4 column within 32-float row

    auto stage = [&](int c) {
        const int buf = c & 1;
        const float* Ag = A + (size_t)bm * INDIM + c * BK;
        const float* Bg = B + (size_t)bn * INDIM + c * BK;
        float* Ad = As + buf * TBUF;
        float* Bd = Bs + buf * TBUF;
#pragma unroll
        for (int u = 0; u < 4; u++) {
            int row = srow + u * 32;
            cp_async16(Ad + row * PITCH + skq * 4,
                       Ag + (size_t)row * INDIM + skq * 4);
        }
#pragma unroll
        for (int u = 0; u < 4; u++) {
            int row = srow + u * 32;
            cp_async16(Bd + row * PITCH + skq * 4,
                       Bg + (size_t)row * INDIM + skq * 4);
        }
        cp_commit();
    };

    stage(0);

    for (int c = 0; c < INDIM / BK; c++) {
        if (c + 1 < INDIM / BK) { stage(c + 1); cp_wait1(); }
        else                    { cp_wait0(); }
        __syncthreads();

        const float* Awp = As + (c & 1) * TBUF + (warp_m * 64) * PITCH;
        const float* Bwp = Bs + (c & 1) * TBUF + (warp_n * 32) * PITCH;

#pragma unroll
        for (int ks = 0; ks < 4; ks++) {
            const int k0 = ks * 8;

            uint32_t ahi[4][4], alo[4][4];
#pragma unroll
            for (int mt = 0; mt < 4; mt++) {
                int r0 = (mt * 16 + g) * PITCH + k0 + tig;
                int r1 = r0 + 8 * PITCH;
                float v0 = Awp[r0], v1 = Awp[r1], v2 = Awp[r0 + 4], v3 = Awp[r1 + 4];
                uint32_t h0 = f32_hi_bits(v0), h1 = f32_hi_bits(v1);
                uint32_t h2 = f32_hi_bits(v2), h3 = f32_hi_bits(v3);
                ahi[mt][0] = h0; ahi[mt][1] = h1; ahi[mt][2] = h2; ahi[mt][3] = h3;
                alo[mt][0] = __float_as_uint(v0 - __uint_as_float(h0));
                alo[mt][1] = __float_as_uint(v1 - __uint_as_float(h1));
                alo[mt][2] = __float_as_uint(v2 - __uint_as_float(h2));
                alo[mt][3] = __float_as_uint(v3 - __uint_as_float(h3));
            }

            uint32_t bhi[4][2], blo[4][2];
#pragma unroll
            for (int nt = 0; nt < 4; nt++) {
                int s0 = (nt * 8 + g) * PITCH + k0 + tig;
                float u0 = Bwp[s0], u1 = Bwp[s0 + 4];
                uint32_t h0 = f32_hi_bits(u0), h1 = f32_hi_bits(u1);
                bhi[nt][0] = h0; bhi[nt][1] = h1;
                blo[nt][0] = __float_as_uint(u0 - __uint_as_float(h0));
                blo[nt][1] = __float_as_uint(u1 - __uint_as_float(h1));
            }

#pragma unroll
            for (int mt = 0; mt < 4; mt++) {
#pragma unroll
                for (int nt = 0; nt < 4; nt++) {
                    mma_tf32(acc[mt][nt],
                             ahi[mt][0], ahi[mt][1], ahi[mt][2], ahi[mt][3],
                             bhi[nt][0], bhi[nt][1]);
                    mma_tf32(acc[mt][nt],
                             alo[mt][0], alo[mt][1], alo[mt][2], alo[mt][3],
                             bhi[nt][0], bhi[nt][1]);
                    mma_tf32(acc[mt][nt],
                             ahi[mt][0], ahi[mt][1], ahi[mt][2], ahi[mt][3],
                             blo[nt][0], blo[nt][1]);
                }
            }
        }
        __syncthreads();
    }

    // ---- epilogue: acc + bias -> C (float2 stores, c0/c1 adjacent in n)
#pragma unroll
    for (int nt = 0; nt < 4; nt++) {
        const int n0 = bn + warp_n * 32 + nt * 8 + 2 * tig;
        const float bv0 = bih[n0] + bhh[n0];
        const float bv1 = bih[n0 + 1] + bhh[n0 + 1];
#pragma unroll
        for (int mt = 0; mt < 4; mt++) {
            const int m0 = bm + warp_m * 64 + mt * 16 + g;
            float2 lo2, hi2;
            lo2.x = acc[mt][nt][0] + bv0;
            lo2.y = acc[mt][nt][1] + bv1;
            hi2.x = acc[mt][nt][2] + bv0;
            hi2.y = acc[mt][nt][3] + bv1;
            *(float2*)(C + (size_t)m0 * HID + n0)       = lo2;
            *(float2*)(C + (size_t)(m0 + 8) * HID + n0) = hi2;
        }
    }
}

// ---------------------------------------------------------------------------
// Phase 2: persistent recurrence (unchanged from R3)
// ---------------------------------------------------------------------------
__global__ __launch_bounds__(RTHREADS) void rnn_recurrence_kernel(
    const float* __restrict__ W,
    float* __restrict__ out)
{
    extern __shared__ float smem[];
    float* Ws      = smem;
    float* hs      = smem + JPB * HID;
    float* scratch = hs + 4 * 2 * 32 * CKP;

    const int tid  = threadIdx.x;
    const int lane = tid & 31;
    const int wid  = tid >> 5;
    const int b    = tid & 63;
    const int kh   = tid >> 6;
    const int brow0 = (wid & 1) * 32;
    const int jbase = blockIdx.x * JPB;

    float* hsw = hs + wid * (2 * 32 * CKP);

    {
        const float4* src = (const float4*)(W + (size_t)blockIdx.x * JPB * HID);
        float4* dst = (float4*)Ws;
#pragma unroll
        for (int u = 0; u < 16; u++)
            dst[tid + RTHREADS * u] = src[tid + RTHREADS * u];
    }
    __syncthreads();

    for (int t = 0; t < SEQ; t++) {
        float* orow = out + ((size_t)t * BATCH + b) * HID + jbase + kh * 4;
        float4 xw = *(const float4*)orow;

        float a0 = 0.f, a1 = 0.f, a2 = 0.f, a3 = 0.f;
        float a4 = 0.f, a5 = 0.f, a6 = 0.f, a7 = 0.f;

        if (t > 0) {
            const float* hprev = out + (size_t)(t - 1) * BATCH * HID;
            const int kbase = kh * 512;

            auto stage = [&](int c) {
                float* buf = hsw + (c & 1) * 32 * CKP;
                const float* src = hprev + (size_t)brow0 * HID + kbase + c * CK + lane * 4;
#pragma unroll
                for (int r = 0; r < 32; r++)
                    cp_async16(buf + r * CKP + lane * 4, src + (size_t)r * HID);
                cp_commit();
            };

            stage(0);
            stage(1);

#pragma unroll
            for (int c = 0; c < NCHUNK; c++) {
                if (c < NCHUNK - 1) cp_wait1(); else cp_wait0();

                const float4* hv = (const float4*)(hsw + (c & 1) * 32 * CKP + lane * CKP);
                const int k0 = kbase + c * CK;
                const float4* w0 = (const float4*)(Ws + 0 * HID + k0);
                const float4* w1 = (const float4*)(Ws + 1 * HID + k0);
                const float4* w2 = (const float4*)(Ws + 2 * HID + k0);
                const float4* w3 = (const float4*)(Ws + 3 * HID + k0);
                const float4* w4 = (const float4*)(Ws + 4 * HID + k0);
                const float4* w5 = (const float4*)(Ws + 5 * HID + k0);
                const float4* w6 = (const float4*)(Ws + 6 * HID + k0);
                const float4* w7 = (const float4*)(Ws + 7 * HID + k0);

#pragma unroll 4
                for (int kk = 0; kk < CK / 4; kk++) {
                    float4 h  = hv[kk];
                    float4 v0 = w0[kk], v1 = w1[kk], v2 = w2[kk], v3 = w3[kk];
                    float4 v4 = w4[kk], v5 = w5[kk], v6 = w6[kk], v7 = w7[kk];
                    a0 = fmaf(h.x, v0.x, a0); a1 = fmaf(h.x, v1.x, a1);
                    a2 = fmaf(h.x, v2.x, a2); a3 = fmaf(h.x, v3.x, a3);
                    a4 = fmaf(h.x, v4.x, a4); a5 = fmaf(h.x, v5.x, a5);
                    a6 = fmaf(h.x, v6.x, a6); a7 = fmaf(h.x, v7.x, a7);
                    a0 = fmaf(h.y, v0.y, a0); a1 = fmaf(h.y, v1.y, a1);
                    a2 = fmaf(h.y, v2.y, a2); a3 = fmaf(h.y, v3.y, a3);
                    a4 = fmaf(h.y, v4.y, a4); a5 = fmaf(h.y, v5.y, a5);
                    a6 = fmaf(h.y, v6.y, a6); a7 = fmaf(h.y, v7.y, a7);
                    a0 = fmaf(h.z, v0.z, a0); a1 = fmaf(h.z, v1.z, a1);
                    a2 = fmaf(h.z, v2.z, a2); a3 = fmaf(h.z, v3.z, a3);
                    a4 = fmaf(h.z, v4.z, a4); a5 = fmaf(h.z, v5.z, a5);
                    a6 = fmaf(h.z, v6.z, a6); a7 = fmaf(h.z, v7.z, a7);
                    a0 = fmaf(h.w, v0.w, a0); a1 = fmaf(h.w, v1.w, a1);
                    a2 = fmaf(h.w, v2.w, a2); a3 = fmaf(h.w, v3.w, a3);
                    a4 = fmaf(h.w, v4.w, a4); a5 = fmaf(h.w, v5.w, a5);
                    a6 = fmaf(h.w, v6.w, a6); a7 = fmaf(h.w, v7.w, a7);
                }

                if (c + 2 < NCHUNK) stage(c + 2);
            }
        }

        __syncthreads();
        {
            float* slot = scratch + (size_t)(kh * 64 + b) * 12;
            *(float4*)(slot + 0) = make_float4(a0, a1, a2, a3);
            *(float4*)(slot + 4) = make_float4(a4, a5, a6, a7);
        }
        __syncthreads();
        {
            const float* other = scratch + (size_t)((1 - kh) * 64 + b) * 12 + kh * 4;
            float4 p = *(const float4*)other;
            float4 own = (kh == 0) ? make_float4(a0, a1, a2, a3)
                                   : make_float4(a4, a5, a6, a7);
            float4 r;
            r.x = tanhf(xw.x + own.x + p.x);
            r.y = tanhf(xw.y + own.y + p.y);
            r.z = tanhf(xw.z + own.z + p.z);
            r.w = tanhf(xw.w + own.w + p.w);
            *(float4*)orow = r;
        }

        if (t < SEQ - 1) {
            __syncthreads();
            if (tid == 0) {
                __threadfence();
                if (atomicAdd(&g_count, 1u) == (unsigned)(gridDim.x - 1)) {
                    atomicExch(&g_count, 0u);
                    __threadfence();
                    g_phase = (unsigned)(t + 1);
                } else {
                    while (g_phase < (unsigned)(t + 1)) { }
                    __threadfence();
                }
            }
            __syncthreads();
        }
    }
}

// ---------------------------------------------------------------------------
__global__ void copy_hn_kernel(const float* __restrict__ src,
                               float* __restrict__ dst)
{
    int i = blockIdx.x * blockDim.x + threadIdx.x;
    float4 v = ((const float4*)src)[i];
    ((float4*)dst)[i] = v;
}

// ---------------------------------------------------------------------------
extern "C" void kernel_launch(void* const* d_in, const int* in_sizes, int n_in,
                              void* d_out, int out_size)
{
    (void)in_sizes; (void)n_in; (void)out_size;
    const float* x    = (const float*)d_in[0];
    const float* W_ih = (const float*)d_in[1];
    const float* W_hh = (const float*)d_in[2];
    const float* b_ih = (const float*)d_in[3];
    const float* b_hh = (const float*)d_in[4];
    float* out = (float*)d_out;

    const int sh_rec = (JPB * HID + 4 * 2 * 32 * CKP + 2 * 64 * 12) * (int)sizeof(float);
    cudaFuncSetAttribute(rnn_recurrence_kernel,
                         cudaFuncAttributeMaxDynamicSharedMemorySize, sh_rec);
    cudaFuncSetAttribute(gemm_xw_mma_kernel,
                         cudaFuncAttributeMaxDynamicSharedMemorySize, SM_GEMM);

    init_sync_kernel<<<1, 1>>>();

    dim3 g1(HID / BN, (SEQ * BATCH) / BM);   // (8, 256)
    gemm_xw_mma_kernel<<<g1, 256, SM_GEMM>>>(x, W_ih, b_ih, b_hh, out);

    rnn_recurrence_kernel<<<RBLK, RTHREADS, sh_rec>>>(W_hh, out);

    copy_hn_kernel<<<(BATCH * HID / 4) / 256, 256>>>(
        out + (size_t)(SEQ - 1) * BATCH * HID,
        out + (size_t)SEQ * BATCH * HID);
}

// round 6
// speedup vs baseline: 2.7393x; 1.1473x over previous
#include <cuda_runtime.h>
#include <math.h>
#include <cstdint>

#define SEQ   512
#define BATCH 64
#define INDIM 1024
#define HID   1024

// ---- phase1 mma.sync tf32 GEMM config ----
#define BM 128
#define BN 128
#define BK 32
#define PITCH 36
#define TBUF (128 * PITCH)
#define SM_GEMM (4 * TBUF * 4)

// ---- recurrence mma config ----
#define RBLK 128       // persistent CTAs
#define JPB  8         // j columns per CTA (one n8 tile)
#define WP   1028      // W row pitch (== 4 mod 32 -> conflict-free)
#define HP   260       // h staging row pitch (== 4 mod 32)
#define CKR  256       // k per staged chunk
#define NCH  4         // chunks (4*256 = 1024)
// SMEM floats: Whi/Wlo 2*8*WP + hs 4*2*16*HP
#define SM_REC_FLOATS (16 * WP + 4 * 2 * 16 * HP)

// ---------------------------------------------------------------------------
__device__ unsigned g_count;
__device__ volatile unsigned g_phase;

__global__ void init_sync_kernel() {
    g_count = 0u;
    g_phase = 0u;
}

// ---------------------------------------------------------------------------
__device__ __forceinline__ void cp_async16(void* smem_dst, const void* gsrc) {
    unsigned d = (unsigned)__cvta_generic_to_shared(smem_dst);
    asm volatile("cp.async.cg.shared.global [%0], [%1], 16;\n" :: "r"(d), "l"(gsrc));
}
__device__ __forceinline__ void cp_commit() { asm volatile("cp.async.commit_group;\n"); }
__device__ __forceinline__ void cp_wait0()  { asm volatile("cp.async.wait_group 0;\n"); }
__device__ __forceinline__ void cp_wait1()  { asm volatile("cp.async.wait_group 1;\n"); }

__device__ __forceinline__ uint32_t f32_hi_bits(float v) {
    return __float_as_uint(v) & 0xFFFFE000u;
}

// D += A(16x8) * B(8x8), tf32 operands as b32 regs
__device__ __forceinline__ void mma_tf32(float* d,
                                         uint32_t a0, uint32_t a1, uint32_t a2, uint32_t a3,
                                         uint32_t b0, uint32_t b1) {
    asm volatile(
        "mma.sync.aligned.m16n8k8.row.col.f32.tf32.tf32.f32 "
        "{%0,%1,%2,%3}, {%4,%5,%6,%7}, {%8,%9}, {%0,%1,%2,%3};"
        : "+f"(d[0]), "+f"(d[1]), "+f"(d[2]), "+f"(d[3])
        : "r"(a0), "r"(a1), "r"(a2), "r"(a3), "r"(b0), "r"(b1));
}

// ---------------------------------------------------------------------------
// Phase 1: C = x @ W_ih^T + (b_ih + b_hh)  via mma.sync tf32 (unchanged R5)
// ---------------------------------------------------------------------------
__global__ __launch_bounds__(256) void gemm_xw_mma_kernel(
    const float* __restrict__ A,
    const float* __restrict__ B,
    const float* __restrict__ bih,
    const float* __restrict__ bhh,
    float* __restrict__ C)
{
    extern __shared__ float sm[];
    float* As = sm;
    float* Bs = sm + 2 * TBUF;

    const int tid    = threadIdx.x;
    const int lane   = tid & 31;
    const int wid    = tid >> 5;
    const int g      = lane >> 2;
    const int tig    = lane & 3;
    const int warp_m = wid & 1;
    const int warp_n = wid >> 1;
    const int bm     = blockIdx.y * BM;
    const int bn     = blockIdx.x * BN;

    float acc[4][4][4];
#pragma unroll
    for (int i = 0; i < 4; i++)
#pragma unroll
        for (int j = 0; j < 4; j++)
#pragma unroll
            for (int c = 0; c < 4; c++) acc[i][j][c] = 0.0f;

    const int srow = tid >> 3;
    const int skq  = tid & 7;

    auto stage = [&](int c) {
        const int buf = c & 1;
        const float* Ag = A + (size_t)bm * INDIM + c * BK;
        const float* Bg = B + (size_t)bn * INDIM + c * BK;
        float* Ad = As + buf * TBUF;
        float* Bd = Bs + buf * TBUF;
#pragma unroll
        for (int u = 0; u < 4; u++) {
            int row = srow + u * 32;
            cp_async16(Ad + row * PITCH + skq * 4,
                       Ag + (size_t)row * INDIM + skq * 4);
        }
#pragma unroll
        for (int u = 0; u < 4; u++) {
            int row = srow + u * 32;
            cp_async16(Bd + row * PITCH + skq * 4,
                       Bg + (size_t)row * INDIM + skq * 4);
        }
        cp_commit();
    };

    stage(0);

    for (int c = 0; c < INDIM / BK; c++) {
        if (c + 1 < INDIM / BK) { stage(c + 1); cp_wait1(); }
        else                    { cp_wait0(); }
        __syncthreads();

        const float* Awp = As + (c & 1) * TBUF + (warp_m * 64) * PITCH;
        const float* Bwp = Bs + (c & 1) * TBUF + (warp_n * 32) * PITCH;

#pragma unroll
        for (int ks = 0; ks < 4; ks++) {
            const int k0 = ks * 8;

            uint32_t ahi[4][4], alo[4][4];
#pragma unroll
            for (int mt = 0; mt < 4; mt++) {
                int r0 = (mt * 16 + g) * PITCH + k0 + tig;
                int r1 = r0 + 8 * PITCH;
                float v0 = Awp[r0], v1 = Awp[r1], v2 = Awp[r0 + 4], v3 = Awp[r1 + 4];
                uint32_t h0 = f32_hi_bits(v0), h1 = f32_hi_bits(v1);
                uint32_t h2 = f32_hi_bits(v2), h3 = f32_hi_bits(v3);
                ahi[mt][0] = h0; ahi[mt][1] = h1; ahi[mt][2] = h2; ahi[mt][3] = h3;
                alo[mt][0] = __float_as_uint(v0 - __uint_as_float(h0));
                alo[mt][1] = __float_as_uint(v1 - __uint_as_float(h1));
                alo[mt][2] = __float_as_uint(v2 - __uint_as_float(h2));
                alo[mt][3] = __float_as_uint(v3 - __uint_as_float(h3));
            }

            uint32_t bhi[4][2], blo[4][2];
#pragma unroll
            for (int nt = 0; nt < 4; nt++) {
                int s0 = (nt * 8 + g) * PITCH + k0 + tig;
                float u0 = Bwp[s0], u1 = Bwp[s0 + 4];
                uint32_t h0 = f32_hi_bits(u0), h1 = f32_hi_bits(u1);
                bhi[nt][0] = h0; bhi[nt][1] = h1;
                blo[nt][0] = __float_as_uint(u0 - __uint_as_float(h0));
                blo[nt][1] = __float_as_uint(u1 - __uint_as_float(h1));
            }

#pragma unroll
            for (int mt = 0; mt < 4; mt++) {
#pragma unroll
                for (int nt = 0; nt < 4; nt++) {
                    mma_tf32(acc[mt][nt],
                             ahi[mt][0], ahi[mt][1], ahi[mt][2], ahi[mt][3],
                             bhi[nt][0], bhi[nt][1]);
                    mma_tf32(acc[mt][nt],
                             alo[mt][0], alo[mt][1], alo[mt][2], alo[mt][3],
                             bhi[nt][0], bhi[nt][1]);
                    mma_tf32(acc[mt][nt],
                             ahi[mt][0], ahi[mt][1], ahi[mt][2], ahi[mt][3],
                             blo[nt][0], blo[nt][1]);
                }
            }
        }
        __syncthreads();
    }

#pragma unroll
    for (int nt = 0; nt < 4; nt++) {
        const int n0 = bn + warp_n * 32 + nt * 8 + 2 * tig;
        const float bv0 = bih[n0] + bhh[n0];
        const float bv1 = bih[n0 + 1] + bhh[n0 + 1];
#pragma unroll
        for (int mt = 0; mt < 4; mt++) {
            const int m0 = bm + warp_m * 64 + mt * 16 + g;
            float2 lo2, hi2;
            lo2.x = acc[mt][nt][0] + bv0;
            lo2.y = acc[mt][nt][1] + bv1;
            hi2.x = acc[mt][nt][2] + bv0;
            hi2.y = acc[mt][nt][3] + bv1;
            *(float2*)(C + (size_t)m0 * HID + n0)       = lo2;
            *(float2*)(C + (size_t)(m0 + 8) * HID + n0) = hi2;
        }
    }
}

// ---------------------------------------------------------------------------
// Phase 2: persistent recurrence via mma.sync tf32 (3-pass split).
//   128 CTAs x 128 threads (4 warps). Warp w: batch rows [16w,16w+16),
//   n8 tile = this CTA's 8 j columns, full K=1024.
//   W_hh rows pre-split hi/lo into SMEM ONCE. h staged warp-private,
//   double-buffered cp.async, split to tf32 at fragment-load time.
// ---------------------------------------------------------------------------
__global__ __launch_bounds__(128) void rnn_rec_mma_kernel(
    const float* __restrict__ W,
    float* __restrict__ out)
{
    extern __shared__ float sm[];
    float* Whi = sm;                 // [8][WP]
    float* Wlo = sm + 8 * WP;        // [8][WP]
    float* hs  = sm + 16 * WP;       // [4 warps][2][16][HP]

    const int tid   = threadIdx.x;
    const int lane  = tid & 31;
    const int w     = tid >> 5;
    const int g     = lane >> 2;     // 0..7
    const int tig   = lane & 3;      // 0..3
    const int jbase = blockIdx.x * JPB;
    const int brow0 = w * 16;

    float* hsw = hs + w * (2 * 16 * HP);

    // ---- pre-split W rows jbase..jbase+7 into hi/lo (once) ----
    for (int i = tid; i < JPB * HID; i += 128) {
        int r = i >> 10, col = i & 1023;
        float v = W[(size_t)(jbase + r) * HID + col];
        uint32_t hb = f32_hi_bits(v);
        Whi[r * WP + col] = __uint_as_float(hb);
        Wlo[r * WP + col] = v - __uint_as_float(hb);
    }
    __syncthreads();

    for (int t = 0; t < SEQ; t++) {
        // xw prefetch (out[t] currently holds xw)
        float* o0 = out + ((size_t)t * BATCH + brow0 + g) * HID + jbase + 2 * tig;
        float* o1 = o0 + (size_t)8 * HID;
        float2 xw0 = *(const float2*)o0;
        float2 xw1 = *(const float2*)o1;

        float ahh[4] = {0.f, 0.f, 0.f, 0.f};
        float alh[4] = {0.f, 0.f, 0.f, 0.f};
        float ahl[4] = {0.f, 0.f, 0.f, 0.f};

        if (t > 0) {
            const float* hprev = out + (size_t)(t - 1) * BATCH * HID
                                     + (size_t)brow0 * HID;

            auto stage = [&](int c) {
                float* buf = hsw + (c & 1) * 16 * HP;
                const float* src = hprev + c * CKR;
#pragma unroll
                for (int r = 0; r < 16; r++) {
                    cp_async16(buf + r * HP + lane * 4,
                               src + (size_t)r * HID + lane * 4);
                    cp_async16(buf + r * HP + (lane + 32) * 4,
                               src + (size_t)r * HID + (lane + 32) * 4);
                }
                cp_commit();
            };

            stage(0);
            stage(1);

            for (int c = 0; c < NCH; c++) {
                if (c < NCH - 1) cp_wait1(); else cp_wait0();

                const float* hb = hsw + (c & 1) * 16 * HP;
                const int kg = c * CKR;

#pragma unroll 4
                for (int k8 = 0; k8 < CKR / 8; k8++) {
                    const int k0 = k8 * 8;
                    // A fragment (h rows, raw fp32 -> split)
                    float v0 = hb[g * HP + k0 + tig];
                    float v1 = hb[(g + 8) * HP + k0 + tig];
                    float v2 = hb[g * HP + k0 + tig + 4];
                    float v3 = hb[(g + 8) * HP + k0 + tig + 4];
                    uint32_t h0 = f32_hi_bits(v0), h1 = f32_hi_bits(v1);
                    uint32_t h2 = f32_hi_bits(v2), h3 = f32_hi_bits(v3);
                    uint32_t l0 = __float_as_uint(v0 - __uint_as_float(h0));
                    uint32_t l1 = __float_as_uint(v1 - __uint_as_float(h1));
                    uint32_t l2 = __float_as_uint(v2 - __uint_as_float(h2));
                    uint32_t l3 = __float_as_uint(v3 - __uint_as_float(h3));
                    // B fragment (W row j = jbase+g), pre-split
                    uint32_t bh0 = __float_as_uint(Whi[g * WP + kg + k0 + tig]);
                    uint32_t bh1 = __float_as_uint(Whi[g * WP + kg + k0 + tig + 4]);
                    uint32_t bl0 = __float_as_uint(Wlo[g * WP + kg + k0 + tig]);
                    uint32_t bl1 = __float_as_uint(Wlo[g * WP + kg + k0 + tig + 4]);

                    mma_tf32(ahh, h0, h1, h2, h3, bh0, bh1);
                    mma_tf32(alh, l0, l1, l2, l3, bh0, bh1);
                    mma_tf32(ahl, h0, h1, h2, h3, bl0, bl1);
                }

                if (c + 2 < NCH) stage(c + 2);
            }
        }

        // ---- epilogue: sum passes, tanh, store h_t in place ----
        {
            float c0 = ahh[0] + alh[0] + ahl[0];
            float c1 = ahh[1] + alh[1] + ahl[1];
            float c2 = ahh[2] + alh[2] + ahl[2];
            float c3 = ahh[3] + alh[3] + ahl[3];
            float2 r0, r1;
            r0.x = tanhf(xw0.x + c0);
            r0.y = tanhf(xw0.y + c1);
            r1.x = tanhf(xw1.x + c2);
            r1.y = tanhf(xw1.y + c3);
            *(float2*)o0 = r0;
            *(float2*)o1 = r1;
        }

        // ---- grid barrier ----
        if (t < SEQ - 1) {
            __syncthreads();
            if (tid == 0) {
                __threadfence();
                if (atomicAdd(&g_count, 1u) == (unsigned)(gridDim.x - 1)) {
                    atomicExch(&g_count, 0u);
                    __threadfence();
                    g_phase = (unsigned)(t + 1);
                } else {
                    while (g_phase < (unsigned)(t + 1)) { }
                    __threadfence();
                }
            }
            __syncthreads();
        }
    }
}

// ---------------------------------------------------------------------------
__global__ void copy_hn_kernel(const float* __restrict__ src,
                               float* __restrict__ dst)
{
    int i = blockIdx.x * blockDim.x + threadIdx.x;
    float4 v = ((const float4*)src)[i];
    ((float4*)dst)[i] = v;
}

// ---------------------------------------------------------------------------
extern "C" void kernel_launch(void* const* d_in, const int* in_sizes, int n_in,
                              void* d_out, int out_size)
{
    (void)in_sizes; (void)n_in; (void)out_size;
    const float* x    = (const float*)d_in[0];
    const float* W_ih = (const float*)d_in[1];
    const float* W_hh = (const float*)d_in[2];
    const float* b_ih = (const float*)d_in[3];
    const float* b_hh = (const float*)d_in[4];
    float* out = (float*)d_out;

    const int sh_rec = SM_REC_FLOATS * (int)sizeof(float);   // 198912 B
    cudaFuncSetAttribute(rnn_rec_mma_kernel,
                         cudaFuncAttributeMaxDynamicSharedMemorySize, sh_rec);
    cudaFuncSetAttribute(gemm_xw_mma_kernel,
                         cudaFuncAttributeMaxDynamicSharedMemorySize, SM_GEMM);

    init_sync_kernel<<<1, 1>>>();

    dim3 g1(HID / BN, (SEQ * BATCH) / BM);
    gemm_xw_mma_kernel<<<g1, 256, SM_GEMM>>>(x, W_ih, b_ih, b_hh, out);

    rnn_rec_mma_kernel<<<RBLK, 128, sh_rec>>>(W_hh, out);

    copy_hn_kernel<<<(BATCH * HID / 4) / 256, 256>>>(
        out + (size_t)(SEQ - 1) * BATCH * HID,
        out + (size_t)SEQ * BATCH * HID);
}

// round 7
// speedup vs baseline: 3.1113x; 1.1358x over previous
#include <cuda_runtime.h>
#include <math.h>
#include <cstdint>

#define SEQ   512
#define BATCH 64
#define INDIM 1024
#define HID   1024

// ---- phase1 mma.sync tf32 GEMM config ----
#define BM 128
#define BN 128
#define BK 32
#define PITCH 36
#define TBUF (128 * PITCH)
#define SM_GEMM (4 * TBUF * 4)

// ---- recurrence mma config (8 warps, k-split) ----
#define RBLK 128
#define JPB  8
#define WP   1028            // W row pitch (== 4 mod 32)
#define HP2  132             // h staging row pitch (== 4 mod 32)
#define CKR2 128             // k per staged chunk
#define NCH2 4               // chunks per k-half (4*128 = 512)
// floats: W hi/lo 16*WP | hs 8 warps * 2 bufs * 16 rows * HP2 | scratch 4*32*5
#define SM_REC_FLOATS (16 * WP + 8 * 2 * 16 * HP2 + 640)

// ---------------------------------------------------------------------------
__device__ unsigned g_count;
__device__ volatile unsigned g_phase;

__global__ void init_sync_kernel() {
    g_count = 0u;
    g_phase = 0u;
}

// ---------------------------------------------------------------------------
__device__ __forceinline__ void cp_async16(void* smem_dst, const void* gsrc) {
    unsigned d = (unsigned)__cvta_generic_to_shared(smem_dst);
    asm volatile("cp.async.cg.shared.global [%0], [%1], 16;\n" :: "r"(d), "l"(gsrc));
}
__device__ __forceinline__ void cp_commit() { asm volatile("cp.async.commit_group;\n"); }
__device__ __forceinline__ void cp_wait0()  { asm volatile("cp.async.wait_group 0;\n"); }
__device__ __forceinline__ void cp_wait1()  { asm volatile("cp.async.wait_group 1;\n"); }

__device__ __forceinline__ uint32_t f32_hi_bits(float v) {
    return __float_as_uint(v) & 0xFFFFE000u;
}

__device__ __forceinline__ void mma_tf32(float* d,
                                         uint32_t a0, uint32_t a1, uint32_t a2, uint32_t a3,
                                         uint32_t b0, uint32_t b1) {
    asm volatile(
        "mma.sync.aligned.m16n8k8.row.col.f32.tf32.tf32.f32 "
        "{%0,%1,%2,%3}, {%4,%5,%6,%7}, {%8,%9}, {%0,%1,%2,%3};"
        : "+f"(d[0]), "+f"(d[1]), "+f"(d[2]), "+f"(d[3])
        : "r"(a0), "r"(a1), "r"(a2), "r"(a3), "r"(b0), "r"(b1));
}

// ---------------------------------------------------------------------------
// Phase 1: C = x @ W_ih^T + (b_ih + b_hh)  via mma.sync tf32 (unchanged)
// ---------------------------------------------------------------------------
__global__ __launch_bounds__(256) void gemm_xw_mma_kernel(
    const float* __restrict__ A,
    const float* __restrict__ B,
    const float* __restrict__ bih,
    const float* __restrict__ bhh,
    float* __restrict__ C)
{
    extern __shared__ float sm[];
    float* As = sm;
    float* Bs = sm + 2 * TBUF;

    const int tid    = threadIdx.x;
    const int lane   = tid & 31;
    const int wid    = tid >> 5;
    const int g      = lane >> 2;
    const int tig    = lane & 3;
    const int warp_m = wid & 1;
    const int warp_n = wid >> 1;
    const int bm     = blockIdx.y * BM;
    const int bn     = blockIdx.x * BN;

    float acc[4][4][4];
#pragma unroll
    for (int i = 0; i < 4; i++)
#pragma unroll
        for (int j = 0; j < 4; j++)
#pragma unroll
            for (int c = 0; c < 4; c++) acc[i][j][c] = 0.0f;

    const int srow = tid >> 3;
    const int skq  = tid & 7;

    auto stage = [&](int c) {
        const int buf = c & 1;
        const float* Ag = A + (size_t)bm * INDIM + c * BK;
        const float* Bg = B + (size_t)bn * INDIM + c * BK;
        float* Ad = As + buf * TBUF;
        float* Bd = Bs + buf * TBUF;
#pragma unroll
        for (int u = 0; u < 4; u++) {
            int row = srow + u * 32;
            cp_async16(Ad + row * PITCH + skq * 4,
                       Ag + (size_t)row * INDIM + skq * 4);
        }
#pragma unroll
        for (int u = 0; u < 4; u++) {
            int row = srow + u * 32;
            cp_async16(Bd + row * PITCH + skq * 4,
                       Bg + (size_t)row * INDIM + skq * 4);
        }
        cp_commit();
    };

    stage(0);

    for (int c = 0; c < INDIM / BK; c++) {
        if (c + 1 < INDIM / BK) { stage(c + 1); cp_wait1(); }
        else                    { cp_wait0(); }
        __syncthreads();

        const float* Awp = As + (c & 1) * TBUF + (warp_m * 64) * PITCH;
        const float* Bwp = Bs + (c & 1) * TBUF + (warp_n * 32) * PITCH;

#pragma unroll
        for (int ks = 0; ks < 4; ks++) {
            const int k0 = ks * 8;

            uint32_t ahi[4][4], alo[4][4];
#pragma unroll
            for (int mt = 0; mt < 4; mt++) {
                int r0 = (mt * 16 + g) * PITCH + k0 + tig;
                int r1 = r0 + 8 * PITCH;
                float v0 = Awp[r0], v1 = Awp[r1], v2 = Awp[r0 + 4], v3 = Awp[r1 + 4];
                uint32_t h0 = f32_hi_bits(v0), h1 = f32_hi_bits(v1);
                uint32_t h2 = f32_hi_bits(v2), h3 = f32_hi_bits(v3);
                ahi[mt][0] = h0; ahi[mt][1] = h1; ahi[mt][2] = h2; ahi[mt][3] = h3;
                alo[mt][0] = __float_as_uint(v0 - __uint_as_float(h0));
                alo[mt][1] = __float_as_uint(v1 - __uint_as_float(h1));
                alo[mt][2] = __float_as_uint(v2 - __uint_as_float(h2));
                alo[mt][3] = __float_as_uint(v3 - __uint_as_float(h3));
            }

            uint32_t bhi[4][2], blo[4][2];
#pragma unroll
            for (int nt = 0; nt < 4; nt++) {
                int s0 = (nt * 8 + g) * PITCH + k0 + tig;
                float u0 = Bwp[s0], u1 = Bwp[s0 + 4];
                uint32_t h0 = f32_hi_bits(u0), h1 = f32_hi_bits(u1);
                bhi[nt][0] = h0; bhi[nt][1] = h1;
                blo[nt][0] = __float_as_uint(u0 - __uint_as_float(h0));
                blo[nt][1] = __float_as_uint(u1 - __uint_as_float(h1));
            }

#pragma unroll
            for (int mt = 0; mt < 4; mt++) {
#pragma unroll
                for (int nt = 0; nt < 4; nt++) {
                    mma_tf32(acc[mt][nt],
                             ahi[mt][0], ahi[mt][1], ahi[mt][2], ahi[mt][3],
                             bhi[nt][0], bhi[nt][1]);
                    mma_tf32(acc[mt][nt],
                             alo[mt][0], alo[mt][1], alo[mt][2], alo[mt][3],
                             bhi[nt][0], bhi[nt][1]);
                    mma_tf32(acc[mt][nt],
                             ahi[mt][0], ahi[mt][1], ahi[mt][2], ahi[mt][3],
                             blo[nt][0], blo[nt][1]);
                }
            }
        }
        __syncthreads();
    }

#pragma unroll
    for (int nt = 0; nt < 4; nt++) {
        const int n0 = bn + warp_n * 32 + nt * 8 + 2 * tig;
        const float bv0 = bih[n0] + bhh[n0];
        const float bv1 = bih[n0 + 1] + bhh[n0 + 1];
#pragma unroll
        for (int mt = 0; mt < 4; mt++) {
            const int m0 = bm + warp_m * 64 + mt * 16 + g;
            float2 lo2, hi2;
            lo2.x = acc[mt][nt][0] + bv0;
            lo2.y = acc[mt][nt][1] + bv1;
            hi2.x = acc[mt][nt][2] + bv0;
            hi2.y = acc[mt][nt][3] + bv1;
            *(float2*)(C + (size_t)m0 * HID + n0)       = lo2;
            *(float2*)(C + (size_t)(m0 + 8) * HID + n0) = hi2;
        }
    }
}

// ---------------------------------------------------------------------------
// Phase 2: persistent recurrence, 8 warps, k-split.
//   warp w: m-tile (w&3)*16 batch rows, k-half (w>>2)*512.
//   Each warp: m16 x n8 x k512, 3-pass tf32 mma, private double-buffered
//   cp.async staging. k-halves combined via SMEM scratch (pitch 5).
// ---------------------------------------------------------------------------
__global__ __launch_bounds__(256) void rnn_rec_mma_kernel(
    const float* __restrict__ W,
    float* __restrict__ out)
{
    extern __shared__ float sm[];
    float* Whi     = sm;                        // [8][WP]
    float* Wlo     = sm + 8 * WP;               // [8][WP]
    float* hs      = sm + 16 * WP;              // [8 warps][2][16][HP2]
    float* scratch = hs + 8 * 2 * 16 * HP2;     // [4][32*5]

    const int tid   = threadIdx.x;
    const int lane  = tid & 31;
    const int w     = tid >> 5;
    const int g     = lane >> 2;
    const int tig   = lane & 3;
    const int jbase = blockIdx.x * JPB;
    const int mrow0 = (w & 3) * 16;
    const int kbase = (w >> 2) * 512;

    float* hsw = hs + w * (2 * 16 * HP2);

    // ---- pre-split W rows jbase..jbase+7 (once) ----
    for (int i = tid; i < JPB * HID; i += 256) {
        int r = i >> 10, col = i & 1023;
        float v = W[(size_t)(jbase + r) * HID + col];
        uint32_t hb = f32_hi_bits(v);
        Whi[r * WP + col] = __uint_as_float(hb);
        Wlo[r * WP + col] = v - __uint_as_float(hb);
    }
    __syncthreads();

    for (int t = 0; t < SEQ; t++) {
        float* o0 = out + ((size_t)t * BATCH + mrow0 + g) * HID + jbase + 2 * tig;
        float* o1 = o0 + (size_t)8 * HID;
        float2 xw0, xw1;
        if (w < 4) {            // only lower warps finalize outputs
            xw0 = *(const float2*)o0;
            xw1 = *(const float2*)o1;
        }

        float ahh[4] = {0.f, 0.f, 0.f, 0.f};
        float alh[4] = {0.f, 0.f, 0.f, 0.f};
        float ahl[4] = {0.f, 0.f, 0.f, 0.f};

        if (t > 0) {
            const float* hprev = out + (size_t)(t - 1) * BATCH * HID
                                     + (size_t)mrow0 * HID + kbase;

            auto stage = [&](int c) {
                float* buf = hsw + (c & 1) * 16 * HP2;
                const float* src = hprev + c * CKR2 + lane * 4;
#pragma unroll
                for (int r = 0; r < 16; r++)
                    cp_async16(buf + r * HP2 + lane * 4, src + (size_t)r * HID);
                cp_commit();
            };

            stage(0);
            stage(1);

#pragma unroll
            for (int c = 0; c < NCH2; c++) {
                if (c < NCH2 - 1) cp_wait1(); else cp_wait0();

                const float* hb = hsw + (c & 1) * 16 * HP2;
                const int kg = kbase + c * CKR2;

#pragma unroll 4
                for (int k8 = 0; k8 < CKR2 / 8; k8++) {
                    const int k0 = k8 * 8;
                    float v0 = hb[g * HP2 + k0 + tig];
                    float v1 = hb[(g + 8) * HP2 + k0 + tig];
                    float v2 = hb[g * HP2 + k0 + tig + 4];
                    float v3 = hb[(g + 8) * HP2 + k0 + tig + 4];
                    uint32_t h0 = f32_hi_bits(v0), h1 = f32_hi_bits(v1);
                    uint32_t h2 = f32_hi_bits(v2), h3 = f32_hi_bits(v3);
                    uint32_t l0 = __float_as_uint(v0 - __uint_as_float(h0));
                    uint32_t l1 = __float_as_uint(v1 - __uint_as_float(h1));
                    uint32_t l2 = __float_as_uint(v2 - __uint_as_float(h2));
                    uint32_t l3 = __float_as_uint(v3 - __uint_as_float(h3));
                    uint32_t bh0 = __float_as_uint(Whi[g * WP + kg + k0 + tig]);
                    uint32_t bh1 = __float_as_uint(Whi[g * WP + kg + k0 + tig + 4]);
                    uint32_t bl0 = __float_as_uint(Wlo[g * WP + kg + k0 + tig]);
                    uint32_t bl1 = __float_as_uint(Wlo[g * WP + kg + k0 + tig + 4]);

                    mma_tf32(ahh, h0, h1, h2, h3, bh0, bh1);
                    mma_tf32(alh, l0, l1, l2, l3, bh0, bh1);
                    mma_tf32(ahl, h0, h1, h2, h3, bl0, bl1);
                }

                if (c + 2 < NCH2) stage(c + 2);
            }
        }

        // ---- combine k-halves via scratch (upper -> lower), tanh, store ----
        if (w >= 4) {
            float* s = scratch + (w - 4) * 160 + lane * 5;
            s[0] = ahh[0] + alh[0] + ahl[0];
            s[1] = ahh[1] + alh[1] + ahl[1];
            s[2] = ahh[2] + alh[2] + ahl[2];
            s[3] = ahh[3] + alh[3] + ahl[3];
        }
        __syncthreads();
        if (w < 4) {
            const float* s = scratch + w * 160 + lane * 5;
            float c0 = ahh[0] + alh[0] + ahl[0] + s[0];
            float c1 = ahh[1] + alh[1] + ahl[1] + s[1];
            float c2 = ahh[2] + alh[2] + ahl[2] + s[2];
            float c3 = ahh[3] + alh[3] + ahl[3] + s[3];
            float2 r0, r1;
            r0.x = tanhf(xw0.x + c0);
            r0.y = tanhf(xw0.y + c1);
            r1.x = tanhf(xw1.x + c2);
            r1.y = tanhf(xw1.y + c3);
            *(float2*)o0 = r0;
            *(float2*)o1 = r1;
        }

        // ---- grid barrier ----
        if (t < SEQ - 1) {
            __syncthreads();
            if (tid == 0) {
                __threadfence();
                if (atomicAdd(&g_count, 1u) == (unsigned)(gridDim.x - 1)) {
                    atomicExch(&g_count, 0u);
                    __threadfence();
                    g_phase = (unsigned)(t + 1);
                } else {
                    while (g_phase < (unsigned)(t + 1)) { }
                    __threadfence();
                }
            }
            __syncthreads();
        }
    }
}

// ---------------------------------------------------------------------------
__global__ void copy_hn_kernel(const float* __restrict__ src,
                               float* __restrict__ dst)
{
    int i = blockIdx.x * blockDim.x + threadIdx.x;
    float4 v = ((const float4*)src)[i];
    ((float4*)dst)[i] = v;
}

// ---------------------------------------------------------------------------
extern "C" void kernel_launch(void* const* d_in, const int* in_sizes, int n_in,
                              void* d_out, int out_size)
{
    (void)in_sizes; (void)n_in; (void)out_size;
    const float* x    = (const float*)d_in[0];
    const float* W_ih = (const float*)d_in[1];
    const float* W_hh = (const float*)d_in[2];
    const float* b_ih = (const float*)d_in[3];
    const float* b_hh = (const float*)d_in[4];
    float* out = (float*)d_out;

    const int sh_rec = SM_REC_FLOATS * (int)sizeof(float);   // 203520 B
    cudaFuncSetAttribute(rnn_rec_mma_kernel,
                         cudaFuncAttributeMaxDynamicSharedMemorySize, sh_rec);
    cudaFuncSetAttribute(gemm_xw_mma_kernel,
                         cudaFuncAttributeMaxDynamicSharedMemorySize, SM_GEMM);

    init_sync_kernel<<<1, 1>>>();

    dim3 g1(HID / BN, (SEQ * BATCH) / BM);
    gemm_xw_mma_kernel<<<g1, 256, SM_GEMM>>>(x, W_ih, b_ih, b_hh, out);

    rnn_rec_mma_kernel<<<RBLK, 256, sh_rec>>>(W_hh, out);

    copy_hn_kernel<<<(BATCH * HID / 4) / 256, 256>>>(
        out + (size_t)(SEQ - 1) * BATCH * HID,
        out + (size_t)SEQ * BATCH * HID);
}

// round 8
// speedup vs baseline: 3.3861x; 1.0883x over previous
#include <cuda_runtime.h>
#include <cuda_fp16.h>
#include <math.h>
#include <cstdint>

#define SEQ   512
#define BATCH 64
#define INDIM 1024
#define HID   1024

// ---- phase1 mma GEMM config ----
#define BM 128
#define BN 128
#define BK 32
#define PITCH 36
#define TBUF (128 * PITCH)
#define SM_GEMM (4 * TBUF * 4)

// ---- recurrence config ----
#define RBLK 128
#define JPB  8
#define HP2  132             // h staging row pitch (fp32)
#define CKR2 128             // k per staged chunk
#define NCH2 4               // chunks per k-half
#define WPB  2064            // W half-row pitch in BYTES (1032 half)
// byte offsets in recurrence SMEM
#define RSM_WHI   0
#define RSM_WLO   16512
#define RSM_HS    33024                       // fp32: 8*2*16*HP2 floats
#define RSM_SCR   (RSM_HS + 8*2*16*HP2*4)     // 4*160 floats
#define RSM_TOTAL (RSM_SCR + 2560)

// ---------------------------------------------------------------------------
__device__ unsigned g_count;
__device__ volatile unsigned g_phase;

__global__ void init_sync_kernel() {
    g_count = 0u;
    g_phase = 0u;
}

// ---------------------------------------------------------------------------
__device__ __forceinline__ void cp_async16(void* smem_dst, const void* gsrc) {
    unsigned d = (unsigned)__cvta_generic_to_shared(smem_dst);
    asm volatile("cp.async.cg.shared.global [%0], [%1], 16;\n" :: "r"(d), "l"(gsrc));
}
__device__ __forceinline__ void cp_commit() { asm volatile("cp.async.commit_group;\n"); }
__device__ __forceinline__ void cp_wait0()  { asm volatile("cp.async.wait_group 0;\n"); }
__device__ __forceinline__ void cp_wait1()  { asm volatile("cp.async.wait_group 1;\n"); }

// Split float2 -> packed half2 (hi: 10-bit-exact, lo: remainder)
__device__ __forceinline__ void split2(float2 v, uint32_t& hi, uint32_t& lo) {
    float h0 = __uint_as_float(__float_as_uint(v.x) & 0xFFFFE000u);
    float h1 = __uint_as_float(__float_as_uint(v.y) & 0xFFFFE000u);
    __half2 hh = __floats2half2_rn(h0, h1);
    __half2 ll = __floats2half2_rn(v.x - h0, v.y - h1);
    hi = *reinterpret_cast<uint32_t*>(&hh);
    lo = *reinterpret_cast<uint32_t*>(&ll);
}

// D += A(16x16) * B(16x8), fp16 operands, fp32 accum
__device__ __forceinline__ void mma_f16(float* d,
                                        uint32_t a0, uint32_t a1, uint32_t a2, uint32_t a3,
                                        uint32_t b0, uint32_t b1) {
    asm volatile(
        "mma.sync.aligned.m16n8k16.row.col.f32.f16.f16.f32 "
        "{%0,%1,%2,%3}, {%4,%5,%6,%7}, {%8,%9}, {%0,%1,%2,%3};"
        : "+f"(d[0]), "+f"(d[1]), "+f"(d[2]), "+f"(d[3])
        : "r"(a0), "r"(a1), "r"(a2), "r"(a3), "r"(b0), "r"(b1));
}

// ---------------------------------------------------------------------------
// Phase 1: C = x @ W_ih^T + (b_ih + b_hh)  via fp16 3-pass mma.
// ---------------------------------------------------------------------------
__global__ __launch_bounds__(256) void gemm_xw_mma_kernel(
    const float* __restrict__ A,
    const float* __restrict__ B,
    const float* __restrict__ bih,
    const float* __restrict__ bhh,
    float* __restrict__ C)
{
    extern __shared__ float sm[];
    float* As = sm;
    float* Bs = sm + 2 * TBUF;

    const int tid    = threadIdx.x;
    const int lane   = tid & 31;
    const int wid    = tid >> 5;
    const int g      = lane >> 2;
    const int tig    = lane & 3;
    const int warp_m = wid & 1;
    const int warp_n = wid >> 1;
    const int bm     = blockIdx.y * BM;
    const int bn     = blockIdx.x * BN;

    float acc[4][4][4];
#pragma unroll
    for (int i = 0; i < 4; i++)
#pragma unroll
        for (int j = 0; j < 4; j++)
#pragma unroll
            for (int c = 0; c < 4; c++) acc[i][j][c] = 0.0f;

    const int srow = tid >> 3;
    const int skq  = tid & 7;

    auto stage = [&](int c) {
        const int buf = c & 1;
        const float* Ag = A + (size_t)bm * INDIM + c * BK;
        const float* Bg = B + (size_t)bn * INDIM + c * BK;
        float* Ad = As + buf * TBUF;
        float* Bd = Bs + buf * TBUF;
#pragma unroll
        for (int u = 0; u < 4; u++) {
            int row = srow + u * 32;
            cp_async16(Ad + row * PITCH + skq * 4,
                       Ag + (size_t)row * INDIM + skq * 4);
        }
#pragma unroll
        for (int u = 0; u < 4; u++) {
            int row = srow + u * 32;
            cp_async16(Bd + row * PITCH + skq * 4,
                       Bg + (size_t)row * INDIM + skq * 4);
        }
        cp_commit();
    };

    stage(0);

    for (int c = 0; c < INDIM / BK; c++) {
        if (c + 1 < INDIM / BK) { stage(c + 1); cp_wait1(); }
        else                    { cp_wait0(); }
        __syncthreads();

        const float* Awp = As + (c & 1) * TBUF + (warp_m * 64) * PITCH;
        const float* Bwp = Bs + (c & 1) * TBUF + (warp_n * 32) * PITCH;

#pragma unroll
        for (int kg = 0; kg < 2; kg++) {     // two k16 groups per 32-k tile
            const int kb = kg * 16 + 2 * tig;

            uint32_t ahi[4][4], alo[4][4];
#pragma unroll
            for (int mt = 0; mt < 4; mt++) {
                int base = (mt * 16 + g) * PITCH + kb;
                float2 f0 = *(const float2*)&Awp[base];
                float2 f1 = *(const float2*)&Awp[base + 8 * PITCH];
                float2 f2 = *(const float2*)&Awp[base + 8];
                float2 f3 = *(const float2*)&Awp[base + 8 * PITCH + 8];
                split2(f0, ahi[mt][0], alo[mt][0]);
                split2(f1, ahi[mt][1], alo[mt][1]);
                split2(f2, ahi[mt][2], alo[mt][2]);
                split2(f3, ahi[mt][3], alo[mt][3]);
            }

            uint32_t bhi[4][2], blo[4][2];
#pragma unroll
            for (int nt = 0; nt < 4; nt++) {
                int sb = (nt * 8 + g) * PITCH + kb;
                float2 u0 = *(const float2*)&Bwp[sb];
                float2 u1 = *(const float2*)&Bwp[sb + 8];
                split2(u0, bhi[nt][0], blo[nt][0]);
                split2(u1, bhi[nt][1], blo[nt][1]);
            }

#pragma unroll
            for (int mt = 0; mt < 4; mt++) {
#pragma unroll
                for (int nt = 0; nt < 4; nt++) {
                    mma_f16(acc[mt][nt],
                            ahi[mt][0], ahi[mt][1], ahi[mt][2], ahi[mt][3],
                            bhi[nt][0], bhi[nt][1]);
                    mma_f16(acc[mt][nt],
                            alo[mt][0], alo[mt][1], alo[mt][2], alo[mt][3],
                            bhi[nt][0], bhi[nt][1]);
                    mma_f16(acc[mt][nt],
                            ahi[mt][0], ahi[mt][1], ahi[mt][2], ahi[mt][3],
                            blo[nt][0], blo[nt][1]);
                }
            }
        }
        __syncthreads();
    }

#pragma unroll
    for (int nt = 0; nt < 4; nt++) {
        const int n0 = bn + warp_n * 32 + nt * 8 + 2 * tig;
        const float bv0 = bih[n0] + bhh[n0];
        const float bv1 = bih[n0 + 1] + bhh[n0 + 1];
#pragma unroll
        for (int mt = 0; mt < 4; mt++) {
            const int m0 = bm + warp_m * 64 + mt * 16 + g;
            float2 lo2, hi2;
            lo2.x = acc[mt][nt][0] + bv0;
            lo2.y = acc[mt][nt][1] + bv1;
            hi2.x = acc[mt][nt][2] + bv0;
            hi2.y = acc[mt][nt][3] + bv1;
            *(float2*)(C + (size_t)m0 * HID + n0)       = lo2;
            *(float2*)(C + (size_t)(m0 + 8) * HID + n0) = hi2;
        }
    }
}

// ---------------------------------------------------------------------------
// Phase 2: persistent recurrence, fp16 3-pass mma, 8 warps k-split.
//   W_hh pre-split (hi/lo half) into SMEM once. h split at frag-load.
// ---------------------------------------------------------------------------
__global__ __launch_bounds__(256) void rnn_rec_mma_kernel(
    const float* __restrict__ W,
    float* __restrict__ out)
{
    extern __shared__ char smb[];
    char*  WhiB    = smb + RSM_WHI;
    char*  WloB    = smb + RSM_WLO;
    float* hs      = (float*)(smb + RSM_HS);
    float* scratch = (float*)(smb + RSM_SCR);

    const int tid   = threadIdx.x;
    const int lane  = tid & 31;
    const int w     = tid >> 5;
    const int g     = lane >> 2;
    const int tig   = lane & 3;
    const int jbase = blockIdx.x * JPB;
    const int mrow0 = (w & 3) * 16;
    const int kbase = (w >> 2) * 512;

    float* hsw = hs + w * (2 * 16 * HP2);

    // ---- pre-split W rows jbase..jbase+7 into fp16 hi/lo (once) ----
    for (int i = tid; i < JPB * HID; i += 256) {
        int r = i >> 10, col = i & 1023;
        float v = W[(size_t)(jbase + r) * HID + col];
        float h32 = __uint_as_float(__float_as_uint(v) & 0xFFFFE000u);
        *(__half*)(WhiB + r * WPB + col * 2) = __float2half_rn(h32);
        *(__half*)(WloB + r * WPB + col * 2) = __float2half_rn(v - h32);
    }
    __syncthreads();

    for (int t = 0; t < SEQ; t++) {
        float* o0 = out + ((size_t)t * BATCH + mrow0 + g) * HID + jbase + 2 * tig;
        float* o1 = o0 + (size_t)8 * HID;
        float2 xw0, xw1;
        if (w < 4) {
            xw0 = *(const float2*)o0;
            xw1 = *(const float2*)o1;
        }

        float ahh[4] = {0.f, 0.f, 0.f, 0.f};
        float alh[4] = {0.f, 0.f, 0.f, 0.f};
        float ahl[4] = {0.f, 0.f, 0.f, 0.f};

        if (t > 0) {
            const float* hprev = out + (size_t)(t - 1) * BATCH * HID
                                     + (size_t)mrow0 * HID + kbase;

            auto stage = [&](int c) {
                float* buf = hsw + (c & 1) * 16 * HP2;
                const float* src = hprev + c * CKR2 + lane * 4;
#pragma unroll
                for (int r = 0; r < 16; r++)
                    cp_async16(buf + r * HP2 + lane * 4, src + (size_t)r * HID);
                cp_commit();
            };

            stage(0);
            stage(1);

#pragma unroll
            for (int c = 0; c < NCH2; c++) {
                if (c < NCH2 - 1) cp_wait1(); else cp_wait0();

                const float* hb = hsw + (c & 1) * 16 * HP2;
                const int kgl = kbase + c * CKR2;   // global k of chunk start

#pragma unroll 4
                for (int kk = 0; kk < CKR2 / 16; kk++) {
                    const int k0 = kk * 16 + 2 * tig;
                    float2 f0 = *(const float2*)&hb[g * HP2 + k0];
                    float2 f1 = *(const float2*)&hb[(g + 8) * HP2 + k0];
                    float2 f2 = *(const float2*)&hb[g * HP2 + k0 + 8];
                    float2 f3 = *(const float2*)&hb[(g + 8) * HP2 + k0 + 8];
                    uint32_t ah0, ah1, ah2, ah3, al0, al1, al2, al3;
                    split2(f0, ah0, al0);
                    split2(f1, ah1, al1);
                    split2(f2, ah2, al2);
                    split2(f3, ah3, al3);

                    const int wb = (kgl + kk * 16 + 2 * tig) * 2;  // byte off in W row
                    uint32_t bh0 = *(const uint32_t*)(WhiB + g * WPB + wb);
                    uint32_t bh1 = *(const uint32_t*)(WhiB + g * WPB + wb + 16);
                    uint32_t bl0 = *(const uint32_t*)(WloB + g * WPB + wb);
                    uint32_t bl1 = *(const uint32_t*)(WloB + g * WPB + wb + 16);

                    mma_f16(ahh, ah0, ah1, ah2, ah3, bh0, bh1);
                    mma_f16(alh, al0, al1, al2, al3, bh0, bh1);
                    mma_f16(ahl, ah0, ah1, ah2, ah3, bl0, bl1);
                }

                if (c + 2 < NCH2) stage(c + 2);
            }
        }

        // ---- combine k-halves via scratch, tanh, store ----
        if (w >= 4) {
            float* s = scratch + (w - 4) * 160 + lane * 5;
            s[0] = ahh[0] + alh[0] + ahl[0];
            s[1] = ahh[1] + alh[1] + ahl[1];
            s[2] = ahh[2] + alh[2] + ahl[2];
            s[3] = ahh[3] + alh[3] + ahl[3];
        }
        __syncthreads();
        if (w < 4) {
            const float* s = scratch + w * 160 + lane * 5;
            float c0 = ahh[0] + alh[0] + ahl[0] + s[0];
            float c1 = ahh[1] + alh[1] + ahl[1] + s[1];
            float c2 = ahh[2] + alh[2] + ahl[2] + s[2];
            float c3 = ahh[3] + alh[3] + ahl[3] + s[3];
            float2 r0, r1;
            r0.x = tanhf(xw0.x + c0);
            r0.y = tanhf(xw0.y + c1);
            r1.x = tanhf(xw1.x + c2);
            r1.y = tanhf(xw1.y + c3);
            *(float2*)o0 = r0;
            *(float2*)o1 = r1;
        }

        // ---- grid barrier (monotonic count) ----
        if (t < SEQ - 1) {
            __syncthreads();
            if (tid == 0) {
                __threadfence();
                if (atomicAdd(&g_count, 1u) == (unsigned)(RBLK * (t + 1) - 1)) {
                    g_phase = (unsigned)(t + 1);
                } else {
                    while (g_phase < (unsigned)(t + 1)) { }
                    __threadfence();
                }
            }
            __syncthreads();
        }
    }
}

// ---------------------------------------------------------------------------
__global__ void copy_hn_kernel(const float* __restrict__ src,
                               float* __restrict__ dst)
{
    int i = blockIdx.x * blockDim.x + threadIdx.x;
    float4 v = ((const float4*)src)[i];
    ((float4*)dst)[i] = v;
}

// ---------------------------------------------------------------------------
extern "C" void kernel_launch(void* const* d_in, const int* in_sizes, int n_in,
                              void* d_out, int out_size)
{
    (void)in_sizes; (void)n_in; (void)out_size;
    const float* x    = (const float*)d_in[0];
    const float* W_ih = (const float*)d_in[1];
    const float* W_hh = (const float*)d_in[2];
    const float* b_ih = (const float*)d_in[3];
    const float* b_hh = (const float*)d_in[4];
    float* out = (float*)d_out;

    cudaFuncSetAttribute(rnn_rec_mma_kernel,
                         cudaFuncAttributeMaxDynamicSharedMemorySize, RSM_TOTAL);
    cudaFuncSetAttribute(gemm_xw_mma_kernel,
                         cudaFuncAttributeMaxDynamicSharedMemorySize, SM_GEMM);

    init_sync_kernel<<<1, 1>>>();

    dim3 g1(HID / BN, (SEQ * BATCH) / BM);
    gemm_xw_mma_kernel<<<g1, 256, SM_GEMM>>>(x, W_ih, b_ih, b_hh, out);

    rnn_rec_mma_kernel<<<RBLK, 256, RSM_TOTAL>>>(W_hh, out);

    copy_hn_kernel<<<(BATCH * HID / 4) / 256, 256>>>(
        out + (size_t)(SEQ - 1) * BATCH * HID,
        out + (size_t)SEQ * BATCH * HID);
}

// round 9
// speedup vs baseline: 3.5983x; 1.0627x over previous
#include <cuda_runtime.h>
#include <cuda_fp16.h>
#include <math.h>
#include <cstdint>

#define SEQ   512
#define BATCH 64
#define INDIM 1024
#define HID   1024

// ---------------- device scratch (static: allowed) ----------------
__device__ __half g_Xhi[SEQ * BATCH * INDIM];   // 64MB
__device__ __half g_Xlo[SEQ * BATCH * INDIM];   // 64MB
__device__ __half g_Whi[HID * INDIM];           // 2MB
__device__ __half g_Wlo[HID * INDIM];           // 2MB
__device__ __half g_Hhi[2][BATCH * HID];        // double-buffered split h
__device__ __half g_Hlo[2][BATCH * HID];

__device__ unsigned g_count;
__device__ volatile unsigned g_phase;

__global__ void init_sync_kernel() {
    g_count = 0u;
    g_phase = 0u;
}

// ---------------------------------------------------------------------------
__device__ __forceinline__ void cp_async16(void* smem_dst, const void* gsrc) {
    unsigned d = (unsigned)__cvta_generic_to_shared(smem_dst);
    asm volatile("cp.async.cg.shared.global [%0], [%1], 16;\n" :: "r"(d), "l"(gsrc));
}
__device__ __forceinline__ void cp_commit() { asm volatile("cp.async.commit_group;\n"); }
__device__ __forceinline__ void cp_wait0()  { asm volatile("cp.async.wait_group 0;\n"); }
__device__ __forceinline__ void cp_wait1()  { asm volatile("cp.async.wait_group 1;\n"); }

__device__ __forceinline__ float mask13(float v) {
    return __uint_as_float(__float_as_uint(v) & 0xFFFFE000u);
}

__device__ __forceinline__ void mma_f16(float* d,
                                        uint32_t a0, uint32_t a1, uint32_t a2, uint32_t a3,
                                        uint32_t b0, uint32_t b1) {
    asm volatile(
        "mma.sync.aligned.m16n8k16.row.col.f32.f16.f16.f32 "
        "{%0,%1,%2,%3}, {%4,%5,%6,%7}, {%8,%9}, {%0,%1,%2,%3};"
        : "+f"(d[0]), "+f"(d[1]), "+f"(d[2]), "+f"(d[3])
        : "r"(a0), "r"(a1), "r"(a2), "r"(a3), "r"(b0), "r"(b1));
}

// ---------------------------------------------------------------------------
// Split kernels: fp32 -> fp16 hi/lo planes (hi = 13-bit-masked, exact in fp16)
// ---------------------------------------------------------------------------
__global__ void split_x_kernel(const float* __restrict__ src) {
    int i = blockIdx.x * 256 + threadIdx.x;   // float4 index, n4 = 8388608
    float4 v = ((const float4*)src)[i];
    float h0 = mask13(v.x), h1 = mask13(v.y), h2 = mask13(v.z), h3 = mask13(v.w);
    ((__half2*)g_Xhi)[2 * i]     = __floats2half2_rn(h0, h1);
    ((__half2*)g_Xhi)[2 * i + 1] = __floats2half2_rn(h2, h3);
    ((__half2*)g_Xlo)[2 * i]     = __floats2half2_rn(v.x - h0, v.y - h1);
    ((__half2*)g_Xlo)[2 * i + 1] = __floats2half2_rn(v.z - h2, v.w - h3);
}
__global__ void split_w_kernel(const float* __restrict__ src) {
    int i = blockIdx.x * 256 + threadIdx.x;   // n4 = 262144
    float4 v = ((const float4*)src)[i];
    float h0 = mask13(v.x), h1 = mask13(v.y), h2 = mask13(v.z), h3 = mask13(v.w);
    ((__half2*)g_Whi)[2 * i]     = __floats2half2_rn(h0, h1);
    ((__half2*)g_Whi)[2 * i + 1] = __floats2half2_rn(h2, h3);
    ((__half2*)g_Wlo)[2 * i]     = __floats2half2_rn(v.x - h0, v.y - h1);
    ((__half2*)g_Wlo)[2 * i + 1] = __floats2half2_rn(v.z - h2, v.w - h3);
}

// ---------------------------------------------------------------------------
// Phase 1: C = x @ W_ih^T + bias. Pure fp16 3-pass MMA from pre-split planes.
//   128x128 block, BK=32, 8 warps (2x4), double-buffered cp.async.
//   SMEM halves: Ahi[2][128][40] | Alo | Bhi | Blo  = 81920 bytes.
// ---------------------------------------------------------------------------
#define P1P 40
__global__ __launch_bounds__(256) void gemm_xw_f16_kernel(
    const float* __restrict__ bih,
    const float* __restrict__ bhh,
    float* __restrict__ C)
{
    extern __shared__ __half sh[];
    __half* Ahi = sh;
    __half* Alo = sh + 10240;
    __half* Bhi = sh + 20480;
    __half* Blo = sh + 30720;

    const int tid    = threadIdx.x;
    const int lane   = tid & 31;
    const int wid    = tid >> 5;
    const int g      = lane >> 2;
    const int tig    = lane & 3;
    const int warp_m = wid & 1;
    const int warp_n = wid >> 1;
    const int bm     = blockIdx.y * 128;
    const int bn     = blockIdx.x * 128;

    float acc[4][4][4];
#pragma unroll
    for (int i = 0; i < 4; i++)
#pragma unroll
        for (int j = 0; j < 4; j++)
#pragma unroll
            for (int c = 0; c < 4; c++) acc[i][j][c] = 0.0f;

    const int srow = tid >> 2;   // 0..63
    const int sch  = tid & 3;    // 16B chunk within 64B row

    auto stage = [&](int c) {
        const int bo = (c & 1) * 5120;
        const int kc = c * 32;
#pragma unroll
        for (int u = 0; u < 2; u++) {
            int row = srow + u * 64;
            size_t aoff = (size_t)(bm + row) * INDIM + kc + sch * 8;
            size_t boff = (size_t)(bn + row) * INDIM + kc + sch * 8;
            cp_async16(Ahi + bo + row * P1P + sch * 8, g_Xhi + aoff);
            cp_async16(Alo + bo + row * P1P + sch * 8, g_Xlo + aoff);
            cp_async16(Bhi + bo + row * P1P + sch * 8, g_Whi + boff);
            cp_async16(Blo + bo + row * P1P + sch * 8, g_Wlo + boff);
        }
        cp_commit();
    };

    stage(0);

    for (int c = 0; c < INDIM / 32; c++) {
        if (c + 1 < INDIM / 32) { stage(c + 1); cp_wait1(); }
        else                    { cp_wait0(); }
        __syncthreads();

        const int bo = (c & 1) * 5120;
        const __half* Aph = Ahi + bo + warp_m * 64 * P1P;
        const __half* Apl = Alo + bo + warp_m * 64 * P1P;
        const __half* Bph = Bhi + bo + warp_n * 32 * P1P;
        const __half* Bpl = Blo + bo + warp_n * 32 * P1P;

#pragma unroll
        for (int kg = 0; kg < 2; kg++) {
            const int ko = kg * 16 + 2 * tig;

            uint32_t ah[4][4], al[4][4];
#pragma unroll
            for (int mt = 0; mt < 4; mt++) {
                int base = (mt * 16 + g) * P1P + ko;
                ah[mt][0] = *(const uint32_t*)&Aph[base];
                ah[mt][1] = *(const uint32_t*)&Aph[base + 8 * P1P];
                ah[mt][2] = *(const uint32_t*)&Aph[base + 8];
                ah[mt][3] = *(const uint32_t*)&Aph[base + 8 * P1P + 8];
                al[mt][0] = *(const uint32_t*)&Apl[base];
                al[mt][1] = *(const uint32_t*)&Apl[base + 8 * P1P];
                al[mt][2] = *(const uint32_t*)&Apl[base + 8];
                al[mt][3] = *(const uint32_t*)&Apl[base + 8 * P1P + 8];
            }
            uint32_t bh[4][2], bl[4][2];
#pragma unroll
            for (int nt = 0; nt < 4; nt++) {
                int sb = (nt * 8 + g) * P1P + ko;
                bh[nt][0] = *(const uint32_t*)&Bph[sb];
                bh[nt][1] = *(const uint32_t*)&Bph[sb + 8];
                bl[nt][0] = *(const uint32_t*)&Bpl[sb];
                bl[nt][1] = *(const uint32_t*)&Bpl[sb + 8];
            }
#pragma unroll
            for (int mt = 0; mt < 4; mt++) {
#pragma unroll
                for (int nt = 0; nt < 4; nt++) {
                    mma_f16(acc[mt][nt], ah[mt][0], ah[mt][1], ah[mt][2], ah[mt][3],
                            bh[nt][0], bh[nt][1]);
                    mma_f16(acc[mt][nt], al[mt][0], al[mt][1], al[mt][2], al[mt][3],
                            bh[nt][0], bh[nt][1]);
                    mma_f16(acc[mt][nt], ah[mt][0], ah[mt][1], ah[mt][2], ah[mt][3],
                            bl[nt][0], bl[nt][1]);
                }
            }
        }
        __syncthreads();
    }

#pragma unroll
    for (int nt = 0; nt < 4; nt++) {
        const int n0 = bn + warp_n * 32 + nt * 8 + 2 * tig;
        const float bv0 = bih[n0] + bhh[n0];
        const float bv1 = bih[n0 + 1] + bhh[n0 + 1];
#pragma unroll
        for (int mt = 0; mt < 4; mt++) {
            const int m0 = bm + warp_m * 64 + mt * 16 + g;
            float2 lo2, hi2;
            lo2.x = acc[mt][nt][0] + bv0;
            lo2.y = acc[mt][nt][1] + bv1;
            hi2.x = acc[mt][nt][2] + bv0;
            hi2.y = acc[mt][nt][3] + bv1;
            *(float2*)(C + (size_t)m0 * HID + n0)       = lo2;
            *(float2*)(C + (size_t)(m0 + 8) * HID + n0) = hi2;
        }
    }
}

// ---------------------------------------------------------------------------
// Phase 2: persistent recurrence. 64 CTAs x 256 threads (8 warps).
//   warp w: m-tile (w&3)*16 rows, k-half (w>>2)*512; n16 = CTA's 16 j cols.
//   h read as pre-split fp16 planes (g_Hhi/g_Hlo, parity double-buffered);
//   written split at epilogue. W_hh pre-split into SMEM once.
// SMEM halves: WHI[16][1032] | WLO | HS[8w][2buf][2pl][16][136]; + scratch fl.
// ---------------------------------------------------------------------------
#define RW 1032
#define RH 136
#define RSM_BYTES 209920
__global__ __launch_bounds__(256) void rnn_rec_f16_kernel(
    const float* __restrict__ W,
    float* __restrict__ out)
{
    extern __shared__ __half sh[];
    __half* WHI = sh;
    __half* WLO = sh + 16512;
    __half* HS  = sh + 33024;
    float* scratch = (float*)((char*)sh + 205312);   // [4][32][9] floats

    const int tid   = threadIdx.x;
    const int lane  = tid & 31;
    const int w     = tid >> 5;
    const int g     = lane >> 2;
    const int tig   = lane & 3;
    const int jbase = blockIdx.x * 16;
    const int mrow0 = (w & 3) * 16;
    const int kbase = (w >> 2) * 512;

    __half* hsw = HS + w * 8704;

    // ---- pre-split W rows jbase..jbase+15 (once) ----
    for (int i = tid; i < 16 * 1024; i += 256) {
        int r = i >> 10, col = i & 1023;
        float v = W[(size_t)(jbase + r) * HID + col];
        float h = mask13(v);
        WHI[r * RW + col] = __float2half_rn(h);
        WLO[r * RW + col] = __float2half_rn(v - h);
    }
    __syncthreads();

    for (int t = 0; t < SEQ; t++) {
        float* obase = out + ((size_t)t * BATCH + mrow0 + g) * HID + jbase;
        float2 xw0, xw1, xw2, xw3;
        if (w < 4) {
            xw0 = *(const float2*)(obase + 2 * tig);                 // row g,  nt0
            xw1 = *(const float2*)(obase + 8 + 2 * tig);             // row g,  nt1
            xw2 = *(const float2*)(obase + 8 * HID + 2 * tig);       // row g+8, nt0
            xw3 = *(const float2*)(obase + 8 * HID + 8 + 2 * tig);   // row g+8, nt1
        }

        float acc[2][3][4];
#pragma unroll
        for (int a = 0; a < 2; a++)
#pragma unroll
            for (int b = 0; b < 3; b++)
#pragma unroll
                for (int c = 0; c < 4; c++) acc[a][b][c] = 0.0f;

        if (t > 0) {
            const int rp = (t - 1) & 1;
            const __half* SrcHi = g_Hhi[rp];
            const __half* SrcLo = g_Hlo[rp];
            const int ch = lane & 15, r0 = lane >> 4;

            auto stage = [&](int c) {
                __half* dh = hsw + (c & 1) * 4352;
                __half* dl = dh + 2176;
                const int kc = kbase + c * 128;
#pragma unroll
                for (int u = 0; u < 8; u++) {
                    int r = r0 + 2 * u;
                    size_t soff = (size_t)(mrow0 + r) * HID + kc + ch * 8;
                    cp_async16(dh + r * RH + ch * 8, SrcHi + soff);
                    cp_async16(dl + r * RH + ch * 8, SrcLo + soff);
                }
                cp_commit();
            };

            stage(0);
            stage(1);

#pragma unroll
            for (int c = 0; c < 4; c++) {
                if (c < 3) cp_wait1(); else cp_wait0();

                const __half* hh = hsw + (c & 1) * 4352;
                const __half* hl = hh + 2176;
                const int kw0 = kbase + c * 128;

#pragma unroll
                for (int kk = 0; kk < 8; kk++) {
                    const int ko = kk * 16 + 2 * tig;
                    uint32_t ah0 = *(const uint32_t*)&hh[g * RH + ko];
                    uint32_t ah1 = *(const uint32_t*)&hh[(g + 8) * RH + ko];
                    uint32_t ah2 = *(const uint32_t*)&hh[g * RH + ko + 8];
                    uint32_t ah3 = *(const uint32_t*)&hh[(g + 8) * RH + ko + 8];
                    uint32_t al0 = *(const uint32_t*)&hl[g * RH + ko];
                    uint32_t al1 = *(const uint32_t*)&hl[(g + 8) * RH + ko];
                    uint32_t al2 = *(const uint32_t*)&hl[g * RH + ko + 8];
                    uint32_t al3 = *(const uint32_t*)&hl[(g + 8) * RH + ko + 8];

                    const int wk = kw0 + ko;
                    uint32_t b0h0 = *(const uint32_t*)&WHI[g * RW + wk];
                    uint32_t b0h1 = *(const uint32_t*)&WHI[g * RW + wk + 8];
                    uint32_t b1h0 = *(const uint32_t*)&WHI[(8 + g) * RW + wk];
                    uint32_t b1h1 = *(const uint32_t*)&WHI[(8 + g) * RW + wk + 8];
                    uint32_t b0l0 = *(const uint32_t*)&WLO[g * RW + wk];
                    uint32_t b0l1 = *(const uint32_t*)&WLO[g * RW + wk + 8];
                    uint32_t b1l0 = *(const uint32_t*)&WLO[(8 + g) * RW + wk];
                    uint32_t b1l1 = *(const uint32_t*)&WLO[(8 + g) * RW + wk + 8];

                    mma_f16(acc[0][0], ah0, ah1, ah2, ah3, b0h0, b0h1);
                    mma_f16(acc[1][0], ah0, ah1, ah2, ah3, b1h0, b1h1);
                    mma_f16(acc[0][1], al0, al1, al2, al3, b0h0, b0h1);
                    mma_f16(acc[1][1], al0, al1, al2, al3, b1h0, b1h1);
                    mma_f16(acc[0][2], ah0, ah1, ah2, ah3, b0l0, b0l1);
                    mma_f16(acc[1][2], ah0, ah1, ah2, ah3, b1l0, b1l1);
                }

                if (c + 2 < 4) stage(c + 2);
            }
        }

        // ---- combine passes + k-halves, tanh, store fp32 + split fp16 ----
        float comb[2][4];
#pragma unroll
        for (int nt = 0; nt < 2; nt++)
#pragma unroll
            for (int i = 0; i < 4; i++)
                comb[nt][i] = acc[nt][0][i] + acc[nt][1][i] + acc[nt][2][i];

        if (w >= 4) {
            float* s = scratch + ((w - 4) * 32 + lane) * 9;
            s[0] = comb[0][0]; s[1] = comb[0][1]; s[2] = comb[0][2]; s[3] = comb[0][3];
            s[4] = comb[1][0]; s[5] = comb[1][1]; s[6] = comb[1][2]; s[7] = comb[1][3];
        }
        __syncthreads();
        if (w < 4) {
            const float* s = scratch + (w * 32 + lane) * 9;
            float v00 = tanhf(xw0.x + comb[0][0] + s[0]);
            float v01 = tanhf(xw0.y + comb[0][1] + s[1]);
            float v10 = tanhf(xw1.x + comb[1][0] + s[4]);
            float v11 = tanhf(xw1.y + comb[1][1] + s[5]);
            float v20 = tanhf(xw2.x + comb[0][2] + s[2]);
            float v21 = tanhf(xw2.y + comb[0][3] + s[3]);
            float v30 = tanhf(xw3.x + comb[1][2] + s[6]);
            float v31 = tanhf(xw3.y + comb[1][3] + s[7]);

            *(float2*)(obase + 2 * tig)               = make_float2(v00, v01);
            *(float2*)(obase + 8 + 2 * tig)           = make_float2(v10, v11);
            *(float2*)(obase + 8 * HID + 2 * tig)     = make_float2(v20, v21);
            *(float2*)(obase + 8 * HID + 8 + 2 * tig) = make_float2(v30, v31);

            // split h_t into fp16 planes for next step
            const int wp = t & 1;
            __half* Hh = g_Hhi[wp];
            __half* Hl = g_Hlo[wp];
            const int row0 = mrow0 + g, row1 = row0 + 8;
            const int c0 = jbase + 2 * tig, c1 = jbase + 8 + 2 * tig;
            auto sps = [&](int row, int col, float a, float b) {
                float ha = mask13(a), hb = mask13(b);
                *(__half2*)(Hh + (size_t)row * HID + col) = __floats2half2_rn(ha, hb);
                *(__half2*)(Hl + (size_t)row * HID + col) = __floats2half2_rn(a - ha, b - hb);
            };
            sps(row0, c0, v00, v01);
            sps(row0, c1, v10, v11);
            sps(row1, c0, v20, v21);
            sps(row1, c1, v30, v31);
        }

        // ---- grid barrier ----
        if (t < SEQ - 1) {
            __syncthreads();
            if (tid == 0) {
                __threadfence();
                if (atomicAdd(&g_count, 1u) == (unsigned)(64 * (t + 1) - 1)) {
                    g_phase = (unsigned)(t + 1);
                } else {
                    while (g_phase < (unsigned)(t + 1)) { }
                    __threadfence();
                }
            }
            __syncthreads();
        }
    }
}

// ---------------------------------------------------------------------------
__global__ void copy_hn_kernel(const float* __restrict__ src,
                               float* __restrict__ dst)
{
    int i = blockIdx.x * blockDim.x + threadIdx.x;
    float4 v = ((const float4*)src)[i];
    ((float4*)dst)[i] = v;
}

// ---------------------------------------------------------------------------
extern "C" void kernel_launch(void* const* d_in, const int* in_sizes, int n_in,
                              void* d_out, int out_size)
{
    (void)in_sizes; (void)n_in; (void)out_size;
    const float* x    = (const float*)d_in[0];
    const float* W_ih = (const float*)d_in[1];
    const float* W_hh = (const float*)d_in[2];
    const float* b_ih = (const float*)d_in[3];
    const float* b_hh = (const float*)d_in[4];
    float* out = (float*)d_out;

    cudaFuncSetAttribute(gemm_xw_f16_kernel,
                         cudaFuncAttributeMaxDynamicSharedMemorySize, 81920);
    cudaFuncSetAttribute(rnn_rec_f16_kernel,
                         cudaFuncAttributeMaxDynamicSharedMemorySize, RSM_BYTES);

    init_sync_kernel<<<1, 1>>>();

    split_x_kernel<<<(SEQ * BATCH * INDIM / 4) / 256, 256>>>(x);
    split_w_kernel<<<(HID * INDIM / 4) / 256, 256>>>(W_ih);

    dim3 g1(HID / 128, (SEQ * BATCH) / 128);
    gemm_xw_f16_kernel<<<g1, 256, 81920>>>(b_ih, b_hh, out);

    rnn_rec_f16_kernel<<<64, 256, RSM_BYTES>>>(W_hh, out);

    copy_hn_kernel<<<(BATCH * HID / 4) / 256, 256>>>(
        out + (size_t)(SEQ - 1) * BATCH * HID,
        out + (size_t)SEQ * BATCH * HID);
}

// round 10
// speedup vs baseline: 4.5351x; 1.2603x over previous
#include <cuda_runtime.h>
#include <cuda_fp16.h>
#include <math.h>
#include <cstdint>

#define SEQ   512
#define BATCH 64
#define INDIM 1024
#define HID   1024

// ---------------- device scratch (static: allowed) ----------------
__device__ __half g_Xhi[SEQ * BATCH * INDIM];
__device__ __half g_Xlo[SEQ * BATCH * INDIM];
__device__ __half g_Whi[HID * INDIM];
__device__ __half g_Wlo[HID * INDIM];
__device__ __half g_Hhi[2][BATCH * HID];
__device__ __half g_Hlo[2][BATCH * HID];

__device__ unsigned g_count;
__device__ volatile unsigned g_phase;

__global__ void init_sync_kernel() {
    g_count = 0u;
    g_phase = 0u;
}

// ---------------------------------------------------------------------------
__device__ __forceinline__ void cp_async16(void* smem_dst, const void* gsrc) {
    unsigned d = (unsigned)__cvta_generic_to_shared(smem_dst);
    asm volatile("cp.async.cg.shared.global [%0], [%1], 16;\n" :: "r"(d), "l"(gsrc));
}
__device__ __forceinline__ void cp_commit() { asm volatile("cp.async.commit_group;\n"); }
__device__ __forceinline__ void cp_wait0()  { asm volatile("cp.async.wait_group 0;\n"); }
__device__ __forceinline__ void cp_wait1()  { asm volatile("cp.async.wait_group 1;\n"); }

__device__ __forceinline__ float mask13(float v) {
    return __uint_as_float(__float_as_uint(v) & 0xFFFFE000u);
}

__device__ __forceinline__ void mma_f16(float* d,
                                        uint32_t a0, uint32_t a1, uint32_t a2, uint32_t a3,
                                        uint32_t b0, uint32_t b1) {
    asm volatile(
        "mma.sync.aligned.m16n8k16.row.col.f32.f16.f16.f32 "
        "{%0,%1,%2,%3}, {%4,%5,%6,%7}, {%8,%9}, {%0,%1,%2,%3};"
        : "+f"(d[0]), "+f"(d[1]), "+f"(d[2]), "+f"(d[3])
        : "r"(a0), "r"(a1), "r"(a2), "r"(a3), "r"(b0), "r"(b1));
}

// ---------------------------------------------------------------------------
// Split kernels: fp32 -> fp16 hi/lo planes (hi = 13-bit-masked, exact in fp16)
// ---------------------------------------------------------------------------
__global__ void split_x_kernel(const float* __restrict__ src) {
    int i = blockIdx.x * 256 + threadIdx.x;
    float4 v = ((const float4*)src)[i];
    float h0 = mask13(v.x), h1 = mask13(v.y), h2 = mask13(v.z), h3 = mask13(v.w);
    ((__half2*)g_Xhi)[2 * i]     = __floats2half2_rn(h0, h1);
    ((__half2*)g_Xhi)[2 * i + 1] = __floats2half2_rn(h2, h3);
    ((__half2*)g_Xlo)[2 * i]     = __floats2half2_rn(v.x - h0, v.y - h1);
    ((__half2*)g_Xlo)[2 * i + 1] = __floats2half2_rn(v.z - h2, v.w - h3);
}
__global__ void split_w_kernel(const float* __restrict__ src) {
    int i = blockIdx.x * 256 + threadIdx.x;
    float4 v = ((const float4*)src)[i];
    float h0 = mask13(v.x), h1 = mask13(v.y), h2 = mask13(v.z), h3 = mask13(v.w);
    ((__half2*)g_Whi)[2 * i]     = __floats2half2_rn(h0, h1);
    ((__half2*)g_Whi)[2 * i + 1] = __floats2half2_rn(h2, h3);
    ((__half2*)g_Wlo)[2 * i]     = __floats2half2_rn(v.x - h0, v.y - h1);
    ((__half2*)g_Wlo)[2 * i + 1] = __floats2half2_rn(v.z - h2, v.w - h3);
}

// ---------------------------------------------------------------------------
// Phase 1: C = x @ W_ih^T + bias. Pure fp16 3-pass MMA (unchanged from R9).
// ---------------------------------------------------------------------------
#define P1P 40
__global__ __launch_bounds__(256) void gemm_xw_f16_kernel(
    const float* __restrict__ bih,
    const float* __restrict__ bhh,
    float* __restrict__ C)
{
    extern __shared__ __half sh[];
    __half* Ahi = sh;
    __half* Alo = sh + 10240;
    __half* Bhi = sh + 20480;
    __half* Blo = sh + 30720;

    const int tid    = threadIdx.x;
    const int lane   = tid & 31;
    const int wid    = tid >> 5;
    const int g      = lane >> 2;
    const int tig    = lane & 3;
    const int warp_m = wid & 1;
    const int warp_n = wid >> 1;
    const int bm     = blockIdx.y * 128;
    const int bn     = blockIdx.x * 128;

    float acc[4][4][4];
#pragma unroll
    for (int i = 0; i < 4; i++)
#pragma unroll
        for (int j = 0; j < 4; j++)
#pragma unroll
            for (int c = 0; c < 4; c++) acc[i][j][c] = 0.0f;

    const int srow = tid >> 2;
    const int sch  = tid & 3;

    auto stage = [&](int c) {
        const int bo = (c & 1) * 5120;
        const int kc = c * 32;
#pragma unroll
        for (int u = 0; u < 2; u++) {
            int row = srow + u * 64;
            size_t aoff = (size_t)(bm + row) * INDIM + kc + sch * 8;
            size_t boff = (size_t)(bn + row) * INDIM + kc + sch * 8;
            cp_async16(Ahi + bo + row * P1P + sch * 8, g_Xhi + aoff);
            cp_async16(Alo + bo + row * P1P + sch * 8, g_Xlo + aoff);
            cp_async16(Bhi + bo + row * P1P + sch * 8, g_Whi + boff);
            cp_async16(Blo + bo + row * P1P + sch * 8, g_Wlo + boff);
        }
        cp_commit();
    };

    stage(0);

    for (int c = 0; c < INDIM / 32; c++) {
        if (c + 1 < INDIM / 32) { stage(c + 1); cp_wait1(); }
        else                    { cp_wait0(); }
        __syncthreads();

        const int bo = (c & 1) * 5120;
        const __half* Aph = Ahi + bo + warp_m * 64 * P1P;
        const __half* Apl = Alo + bo + warp_m * 64 * P1P;
        const __half* Bph = Bhi + bo + warp_n * 32 * P1P;
        const __half* Bpl = Blo + bo + warp_n * 32 * P1P;

#pragma unroll
        for (int kg = 0; kg < 2; kg++) {
            const int ko = kg * 16 + 2 * tig;

            uint32_t ah[4][4], al[4][4];
#pragma unroll
            for (int mt = 0; mt < 4; mt++) {
                int base = (mt * 16 + g) * P1P + ko;
                ah[mt][0] = *(const uint32_t*)&Aph[base];
                ah[mt][1] = *(const uint32_t*)&Aph[base + 8 * P1P];
                ah[mt][2] = *(const uint32_t*)&Aph[base + 8];
                ah[mt][3] = *(const uint32_t*)&Aph[base + 8 * P1P + 8];
                al[mt][0] = *(const uint32_t*)&Apl[base];
                al[mt][1] = *(const uint32_t*)&Apl[base + 8 * P1P];
                al[mt][2] = *(const uint32_t*)&Apl[base + 8];
                al[mt][3] = *(const uint32_t*)&Apl[base + 8 * P1P + 8];
            }
            uint32_t bh[4][2], bl[4][2];
#pragma unroll
            for (int nt = 0; nt < 4; nt++) {
                int sb = (nt * 8 + g) * P1P + ko;
                bh[nt][0] = *(const uint32_t*)&Bph[sb];
                bh[nt][1] = *(const uint32_t*)&Bph[sb + 8];
                bl[nt][0] = *(const uint32_t*)&Bpl[sb];
                bl[nt][1] = *(const uint32_t*)&Bpl[sb + 8];
            }
#pragma unroll
            for (int mt = 0; mt < 4; mt++) {
#pragma unroll
                for (int nt = 0; nt < 4; nt++) {
                    mma_f16(acc[mt][nt], ah[mt][0], ah[mt][1], ah[mt][2], ah[mt][3],
                            bh[nt][0], bh[nt][1]);
                    mma_f16(acc[mt][nt], al[mt][0], al[mt][1], al[mt][2], al[mt][3],
                            bh[nt][0], bh[nt][1]);
                    mma_f16(acc[mt][nt], ah[mt][0], ah[mt][1], ah[mt][2], ah[mt][3],
                            bl[nt][0], bl[nt][1]);
                }
            }
        }
        __syncthreads();
    }

#pragma unroll
    for (int nt = 0; nt < 4; nt++) {
        const int n0 = bn + warp_n * 32 + nt * 8 + 2 * tig;
        const float bv0 = bih[n0] + bhh[n0];
        const float bv1 = bih[n0 + 1] + bhh[n0 + 1];
#pragma unroll
        for (int mt = 0; mt < 4; mt++) {
            const int m0 = bm + warp_m * 64 + mt * 16 + g;
            float2 lo2, hi2;
            lo2.x = acc[mt][nt][0] + bv0;
            lo2.y = acc[mt][nt][1] + bv1;
            hi2.x = acc[mt][nt][2] + bv0;
            hi2.y = acc[mt][nt][3] + bv1;
            *(float2*)(C + (size_t)m0 * HID + n0)       = lo2;
            *(float2*)(C + (size_t)(m0 + 8) * HID + n0) = hi2;
        }
    }
}

// ---------------------------------------------------------------------------
// Phase 2: persistent recurrence, (b-tile, j-tile) grid.
//   128 CTAs = (bt 0..3) x (jt 0..31). CTA: m16 batch rows, n32 j cols.
//   8 warps = (nt 0..3) x (kh 0..1). Each warp m16 n8 k512, 3-pass fp16.
//   W slice (32 rows, hi/lo fp16) in SMEM once. h staged CTA-cooperatively:
//   chunk c = k [c*128,+128) of BOTH k-halves, both planes, double-buffered.
// SMEM halves: WHI[32][1032] | WLO | HS[2buf][2pl][2kh][16][136] | scr(fl)
// ---------------------------------------------------------------------------
#define RW  1032
#define RH  136
#define HSB 8704                 // halves per staging buffer
#define RSM_BYTES 169472
__global__ __launch_bounds__(256) void rnn_rec_f16_kernel(
    const float* __restrict__ W,
    float* __restrict__ out)
{
    extern __shared__ __half sh[];
    __half* WHI = sh;                       // 33024 halves
    __half* WLO = sh + 33024;
    __half* HS  = sh + 66048;               // 2 * 8704
    float* scratch = (float*)((char*)sh + 166912);   // [4][32][5] floats

    const int tid   = threadIdx.x;
    const int lane  = tid & 31;
    const int w     = tid >> 5;
    const int g     = lane >> 2;
    const int tig   = lane & 3;
    const int bt    = blockIdx.x & 3;
    const int jt    = blockIdx.x >> 2;
    const int jbase = jt * 32;
    const int mrow0 = bt * 16;
    const int nt    = w >> 1;
    const int kh    = w & 1;
    const int kbase = kh * 512;

    // ---- pre-split W rows jbase..jbase+31 (once) ----
    for (int i = tid; i < 32 * 1024; i += 256) {
        int r = i >> 10, col = i & 1023;
        float v = W[(size_t)(jbase + r) * HID + col];
        float h = mask13(v);
        WHI[r * RW + col] = __float2half_rn(h);
        WLO[r * RW + col] = __float2half_rn(v - h);
    }
    __syncthreads();

    // staging map: pl=tid>>7, kh2=(tid>>6)&1, row=(tid>>2)&15, cc=tid&3
    const int s_pl  = tid >> 7;
    const int s_kh  = (tid >> 6) & 1;
    const int s_row = (tid >> 2) & 15;
    const int s_cc  = tid & 3;

    for (int t = 0; t < SEQ; t++) {
        float* o0 = out + ((size_t)t * BATCH + mrow0 + g) * HID + jbase + nt * 8 + 2 * tig;
        float* o1 = o0 + (size_t)8 * HID;
        float2 xw0, xw1;
        if (kh == 0) {
            xw0 = *(const float2*)o0;
            xw1 = *(const float2*)o1;
        }

        float ahh[4] = {0.f, 0.f, 0.f, 0.f};
        float alh[4] = {0.f, 0.f, 0.f, 0.f};
        float ahl[4] = {0.f, 0.f, 0.f, 0.f};

        if (t > 0) {
            const int rp = (t - 1) & 1;
            const __half* planes[2] = { g_Hhi[rp] + (size_t)mrow0 * HID,
                                        g_Hlo[rp] + (size_t)mrow0 * HID };

            auto stage = [&](int c) {
                __half* dst = HS + (c & 1) * HSB + s_pl * 4352 + s_kh * 2176
                            + s_row * RH;
                const __half* src = planes[s_pl] + (size_t)s_row * HID
                                  + s_kh * 512 + c * 128;
#pragma unroll
                for (int u = 0; u < 4; u++) {
                    int cu = s_cc + u * 4;        // 16B unit within 256B row
                    cp_async16(dst + cu * 8, src + cu * 8);
                }
                cp_commit();
            };

            stage(0);
            stage(1);

#pragma unroll
            for (int c = 0; c < 4; c++) {
                if (c < 3) cp_wait1(); else cp_wait0();
                __syncthreads();

                const __half* hh = HS + (c & 1) * HSB + kh * 2176;
                const __half* hl = hh + 4352;
                const int kw0 = kbase + c * 128;

#pragma unroll
                for (int kk = 0; kk < 8; kk++) {
                    const int ko = kk * 16 + 2 * tig;
                    uint32_t ah0 = *(const uint32_t*)&hh[g * RH + ko];
                    uint32_t ah1 = *(const uint32_t*)&hh[(g + 8) * RH + ko];
                    uint32_t ah2 = *(const uint32_t*)&hh[g * RH + ko + 8];
                    uint32_t ah3 = *(const uint32_t*)&hh[(g + 8) * RH + ko + 8];
                    uint32_t al0 = *(const uint32_t*)&hl[g * RH + ko];
                    uint32_t al1 = *(const uint32_t*)&hl[(g + 8) * RH + ko];
                    uint32_t al2 = *(const uint32_t*)&hl[g * RH + ko + 8];
                    uint32_t al3 = *(const uint32_t*)&hl[(g + 8) * RH + ko + 8];

                    const int wrow = (nt * 8 + g) * RW + kw0 + ko;
                    uint32_t bh0 = *(const uint32_t*)&WHI[wrow];
                    uint32_t bh1 = *(const uint32_t*)&WHI[wrow + 8];
                    uint32_t bl0 = *(const uint32_t*)&WLO[wrow];
                    uint32_t bl1 = *(const uint32_t*)&WLO[wrow + 8];

                    mma_f16(ahh, ah0, ah1, ah2, ah3, bh0, bh1);
                    mma_f16(alh, al0, al1, al2, al3, bh0, bh1);
                    mma_f16(ahl, ah0, ah1, ah2, ah3, bl0, bl1);
                }

                __syncthreads();
                if (c + 2 < 4) stage(c + 2);
            }
        }

        // ---- combine k-halves via scratch, tanh, store fp32 + split fp16 ----
        if (kh == 1) {
            float* s = scratch + (nt * 32 + lane) * 5;
            s[0] = ahh[0] + alh[0] + ahl[0];
            s[1] = ahh[1] + alh[1] + ahl[1];
            s[2] = ahh[2] + alh[2] + ahl[2];
            s[3] = ahh[3] + alh[3] + ahl[3];
        }
        __syncthreads();
        if (kh == 0) {
            const float* s = scratch + (nt * 32 + lane) * 5;
            float v00 = tanhf(xw0.x + ahh[0] + alh[0] + ahl[0] + s[0]);
            float v01 = tanhf(xw0.y + ahh[1] + alh[1] + ahl[1] + s[1]);
            float v10 = tanhf(xw1.x + ahh[2] + alh[2] + ahl[2] + s[2]);
            float v11 = tanhf(xw1.y + ahh[3] + alh[3] + ahl[3] + s[3]);

            *(float2*)o0 = make_float2(v00, v01);
            *(float2*)o1 = make_float2(v10, v11);

            // split h_t into fp16 planes for next step
            const int wp = t & 1;
            __half* Hh = g_Hhi[wp];
            __half* Hl = g_Hlo[wp];
            const size_t i0 = (size_t)(mrow0 + g) * HID + jbase + nt * 8 + 2 * tig;
            const size_t i1 = i0 + (size_t)8 * HID;
            float h00 = mask13(v00), h01 = mask13(v01);
            float h10 = mask13(v10), h11 = mask13(v11);
            *(__half2*)(Hh + i0) = __floats2half2_rn(h00, h01);
            *(__half2*)(Hl + i0) = __floats2half2_rn(v00 - h00, v01 - h01);
            *(__half2*)(Hh + i1) = __floats2half2_rn(h10, h11);
            *(__half2*)(Hl + i1) = __floats2half2_rn(v10 - h10, v11 - h11);
        }

        // ---- grid barrier (monotonic) ----
        if (t < SEQ - 1) {
            __syncthreads();
            if (tid == 0) {
                __threadfence();
                if (atomicAdd(&g_count, 1u) == (unsigned)(128 * (t + 1) - 1)) {
                    g_phase = (unsigned)(t + 1);
                } else {
                    while (g_phase < (unsigned)(t + 1)) { }
                    __threadfence();
                }
            }
            __syncthreads();
        }
    }
}

// ---------------------------------------------------------------------------
__global__ void copy_hn_kernel(const float* __restrict__ src,
                               float* __restrict__ dst)
{
    int i = blockIdx.x * blockDim.x + threadIdx.x;
    float4 v = ((const float4*)src)[i];
    ((float4*)dst)[i] = v;
}

// ---------------------------------------------------------------------------
extern "C" void kernel_launch(void* const* d_in, const int* in_sizes, int n_in,
                              void* d_out, int out_size)
{
    (void)in_sizes; (void)n_in; (void)out_size;
    const float* x    = (const float*)d_in[0];
    const float* W_ih = (const float*)d_in[1];
    const float* W_hh = (const float*)d_in[2];
    const float* b_ih = (const float*)d_in[3];
    const float* b_hh = (const float*)d_in[4];
    float* out = (float*)d_out;

    cudaFuncSetAttribute(gemm_xw_f16_kernel,
                         cudaFuncAttributeMaxDynamicSharedMemorySize, 81920);
    cudaFuncSetAttribute(rnn_rec_f16_kernel,
                         cudaFuncAttributeMaxDynamicSharedMemorySize, RSM_BYTES);

    init_sync_kernel<<<1, 1>>>();

    split_x_kernel<<<(SEQ * BATCH * INDIM / 4) / 256, 256>>>(x);
    split_w_kernel<<<(HID * INDIM / 4) / 256, 256>>>(W_ih);

    dim3 g1(HID / 128, (SEQ * BATCH) / 128);
    gemm_xw_f16_kernel<<<g1, 256, 81920>>>(b_ih, b_hh, out);

    rnn_rec_f16_kernel<<<128, 256, RSM_BYTES>>>(W_hh, out);

    copy_hn_kernel<<<(BATCH * HID / 4) / 256, 256>>>(
        out + (size_t)(SEQ - 1) * BATCH * HID,
        out + (size_t)SEQ * BATCH * HID);
}